// round 13
// baseline (speedup 1.0000x reference)
#include <cuda_runtime.h>
#include <cuda_bf16.h>
#include <cstdint>

// ---------------------------------------------------------------------------
// HybridAttention — round 12: fgemm re-tiled to K-chunk 32 (smem 96KB -> 2
// CTAs/SM, 16 warps resident). Everything else identical to passing R11.
// ---------------------------------------------------------------------------

#define DIMC   192
#define HEADS  8
#define CH     24
#define HH     256
#define WW     256
#define HW     65536
#define HD     32
#define WD     32
#define PD     1024
#define BATCH  4

// ------------------------- scratch (static device) -------------------------
__device__ float g_hcatdw[(size_t)BATCH * 384 * HW];
__device__ float g_cat   [(size_t)BATCH * 384 * HW];
__device__ float g_t4    [(size_t)BATCH * DIMC * HW];
__device__ float g_xdown [(size_t)BATCH * DIMC * PD];
__device__ float g_qkv   [(size_t)BATCH * 576 * PD];
__device__ float g_qkvdw [(size_t)BATCH * 576 * PD];
__device__ float g_attn  [(size_t)BATCH * HEADS * CH * CH];
__device__ float g_gate  [(size_t)BATCH * DIMC];
__device__ __nv_bfloat16 g_w1h[192 * 384], g_w1l[192 * 384];
__device__ __nv_bfloat16 g_w4h[192 * 192], g_w4l[192 * 192];
__device__ __nv_bfloat16 g_wph[192 * 384], g_wpl[192 * 384];

// --------------------------- ptx helpers (sm_80 ISA) ------------------------
__device__ __forceinline__ uint32_t smem_u32(const void* p) {
    uint32_t a;
    asm("{ .reg .u64 t; cvta.to.shared.u64 t, %1; cvt.u32.u64 %0, t; }"
        : "=r"(a) : "l"(p));
    return a;
}
__device__ __forceinline__ void cpasync16(uint32_t saddr, const void* gaddr) {
    asm volatile("cp.async.cg.shared.global [%0], [%1], 16;"
                 :: "r"(saddr), "l"(gaddr));
}
__device__ __forceinline__ void cpcommit() {
    asm volatile("cp.async.commit_group;" ::: "memory");
}
template<int N> __device__ __forceinline__ void cpwait() {
    asm volatile("cp.async.wait_group %0;" :: "n"(N) : "memory");
}
__device__ __forceinline__ void ldsm4(uint32_t* r, uint32_t addr) {
    asm volatile("ldmatrix.sync.aligned.m8n8.x4.shared.b16 {%0,%1,%2,%3}, [%4];"
        : "=r"(r[0]), "=r"(r[1]), "=r"(r[2]), "=r"(r[3]) : "r"(addr));
}
__device__ __forceinline__ void ldsm4t(uint32_t* r, uint32_t addr) {
    asm volatile("ldmatrix.sync.aligned.m8n8.x4.trans.shared.b16 {%0,%1,%2,%3}, [%4];"
        : "=r"(r[0]), "=r"(r[1]), "=r"(r[2]), "=r"(r[3]) : "r"(addr));
}
__device__ __forceinline__ void mma16816(float* d, const uint32_t* a,
                                         uint32_t b0, uint32_t b1) {
    asm volatile(
        "mma.sync.aligned.m16n8k16.row.col.f32.bf16.bf16.f32 "
        "{%0,%1,%2,%3}, {%4,%5,%6,%7}, {%8,%9}, {%0,%1,%2,%3};"
        : "+f"(d[0]), "+f"(d[1]), "+f"(d[2]), "+f"(d[3])
        : "r"(a[0]), "r"(a[1]), "r"(a[2]), "r"(a[3]), "r"(b0), "r"(b1));
}
__device__ __forceinline__ uint32_t pk2(float a, float b) {
    __nv_bfloat162 t; t.x = __float2bfloat16(a); t.y = __float2bfloat16(b);
    return *reinterpret_cast<uint32_t*>(&t);
}

// ------------------------------ MMA-GEMM (K-chunk 32) ------------------------
// D[128 px, 192 outch] = A[K, px]^T @ (Whi+Wlo)[192,K]^T, A fp32 split on load.
#define ASTR  272      // 128 px bf16 = 256B + 16 pad
#define BSTR  80       // 32 k bf16 = 64B + 16 pad
#define ATH   0
#define ATL   8704     // 32*272
#define BH    17408
#define BL    32768    // +192*80
#define SMEM1 48128    // one stage
#define SMEMT (2 * SMEM1)

__device__ __forceinline__ void lda_regs(float4* r, const float* Ab, int k0, int tid) {
    #pragma unroll
    for (int i = 0; i < 4; i++) {
        int e = tid + (i << 8); int k = e >> 5, q = e & 31;
        r[i] = *reinterpret_cast<const float4*>(Ab + (size_t)(k0 + k) * HW + (q << 2));
    }
}
__device__ __forceinline__ void cvt_sts(const float4* r, char* smem, int tid) {
    #pragma unroll
    for (int i = 0; i < 4; i++) {
        int e = tid + (i << 8); int k = e >> 5, q = e & 31;
        float4 f = r[i];
        uint32_t so = (uint32_t)k * ASTR + (q << 3);
        uint2 hv, lv;
        hv.x = pk2(f.x, f.y); hv.y = pk2(f.z, f.w);
        float rx = f.x - __bfloat162float(__float2bfloat16(f.x));
        float ry = f.y - __bfloat162float(__float2bfloat16(f.y));
        float rz = f.z - __bfloat162float(__float2bfloat16(f.z));
        float rw = f.w - __bfloat162float(__float2bfloat16(f.w));
        lv.x = pk2(rx, ry); lv.y = pk2(rz, rw);
        *reinterpret_cast<uint2*>(smem + so + ATH) = hv;
        *reinterpret_cast<uint2*>(smem + so + ATL) = lv;
    }
}
__device__ __forceinline__ void ldb_async(uint32_t sbuf,
    const __nv_bfloat16* Wh, const __nv_bfloat16* Wl, int Ka, int k0, int tid) {
    #pragma unroll
    for (int i = 0; i < 3; i++) {
        int e = tid + (i << 8); int r = e >> 2, q = e & 3;
        size_t go = (size_t)r * Ka + k0 + (q << 3);
        uint32_t so = r * BSTR + (q << 4);
        cpasync16(sbuf + BH + so, Wh + go);
        cpasync16(sbuf + BL + so, Wl + go);
    }
}

__global__ __launch_bounds__(256, 2) void fgemm_kernel(
    const float* __restrict__ In, int Ka,
    const __nv_bfloat16* __restrict__ Whi, const __nv_bfloat16* __restrict__ Wlo,
    float* __restrict__ Out, int chTot, int outOff)
{
    extern __shared__ char smem[];
    const uint32_t sb = smem_u32(smem);
    const int tid = threadIdx.x;
    const int warp = tid >> 5, lane = tid & 31;
    const int mw = warp >> 1, nw = warp & 1;        // 4 (M) x 2 (N) warps
    const int b = blockIdx.z;
    const int px0 = blockIdx.x * 128;
    const int nChunks = Ka >> 5;

    const float* Ab = In + (size_t)b * Ka * HW + px0;

    float acc[2][12][4] = {};

    const int grp = lane >> 3, rr = lane & 7;
    uint32_t aoff[2];
    #pragma unroll
    for (int mt = 0; mt < 2; mt++)
        aoff[mt] = (uint32_t)((grp >> 1) * 8 + rr) * ASTR +
                   (uint32_t)(mw * 32 + mt * 16 + (grp & 1) * 8) * 2;
    const uint32_t boff = (uint32_t)(nw * 96 + rr + (grp >> 1) * 8) * BSTR +
                          (grp & 1) * 16;

    float4 ar[4];
    lda_regs(ar, Ab, 0, tid);
    ldb_async(sb, Whi, Wlo, Ka, 0, tid);
    cpcommit();

    for (int ch = 0; ch < nChunks; ch++) {
        const uint32_t bufo = (uint32_t)(ch & 1) * SMEM1;
        cvt_sts(ar, smem + bufo, tid);
        if (ch + 1 < nChunks) {
            lda_regs(ar, Ab, (ch + 1) << 5, tid);
            ldb_async(sb + ((ch + 1) & 1) * SMEM1, Whi, Wlo, Ka, (ch + 1) << 5, tid);
            cpcommit();
            cpwait<1>();
        } else {
            cpwait<0>();
        }
        __syncthreads();

        const uint32_t buf = sb + bufo;
        #pragma unroll
        for (int ks = 0; ks < 2; ks++) {
            uint32_t ah[2][4], al[2][4];
            ldsm4t(ah[0], buf + ATH + aoff[0] + ks * (16 * ASTR));
            ldsm4t(ah[1], buf + ATH + aoff[1] + ks * (16 * ASTR));
            ldsm4t(al[0], buf + ATL + aoff[0] + ks * (16 * ASTR));
            ldsm4t(al[1], buf + ATL + aoff[1] + ks * (16 * ASTR));
            #pragma unroll
            for (int p = 0; p < 6; p++) {
                uint32_t bh[4], bl[4];
                uint32_t ba = buf + boff + (uint32_t)p * 16 * BSTR + ks * 32;
                ldsm4(bh, ba + BH);
                ldsm4(bl, ba + BL);
                #pragma unroll
                for (int mt = 0; mt < 2; mt++) {
                    mma16816(acc[mt][2 * p],     ah[mt], bh[0], bh[1]);
                    mma16816(acc[mt][2 * p + 1], ah[mt], bh[2], bh[3]);
                    mma16816(acc[mt][2 * p],     ah[mt], bl[0], bl[1]);
                    mma16816(acc[mt][2 * p + 1], ah[mt], bl[2], bl[3]);
                    mma16816(acc[mt][2 * p],     al[mt], bh[0], bh[1]);
                    mma16816(acc[mt][2 * p + 1], al[mt], bh[2], bh[3]);
                }
            }
        }
        __syncthreads();
    }

    // ---- epilogue: fp32 ch-major ----
    const int mrow = lane >> 2;
    const int ncol = 2 * (lane & 3);
    float* ob = Out + ((size_t)b * chTot + outOff) * HW + px0;
    #pragma unroll
    for (int mt = 0; mt < 2; mt++) {
        #pragma unroll
        for (int nt = 0; nt < 12; nt++) {
            int m = mw * 32 + mt * 16 + mrow;
            int n = nw * 96 + nt * 8 + ncol;
            ob[(size_t)n * HW + m]           = acc[mt][nt][0];
            ob[(size_t)(n + 1) * HW + m]     = acc[mt][nt][1];
            ob[(size_t)n * HW + m + 8]       = acc[mt][nt][2];
            ob[(size_t)(n + 1) * HW + m + 8] = acc[mt][nt][3];
        }
    }
}

// ----------------------- weight convert (hi/lo) -----------------------------
__global__ void convw_kernel(const float* __restrict__ w,
                             __nv_bfloat16* __restrict__ hi,
                             __nv_bfloat16* __restrict__ lo, int n)
{
    int i = blockIdx.x * 256 + threadIdx.x;
    if (i >= n) return;
    float v = w[i];
    __nv_bfloat16 h = __float2bfloat16(v);
    hi[i] = h;
    lo[i] = __float2bfloat16(v - __bfloat162float(h));
}

// ------------------------------ fp32 SGEMM (qkv only) ------------------------
#define BM 64
#define BN 128
#define BKK 16

__global__ __launch_bounds__(256) void gemm_kernel(
    const float* __restrict__ Wt, const float* __restrict__ In,
    float* __restrict__ Out, int K, int N, size_t inBS, size_t outBS)
{
    const int b = blockIdx.z;
    const float* Ib = In + (size_t)b * inBS;
    float* Ob = Out + (size_t)b * outBS;
    const int m0 = blockIdx.y * BM;
    const int n0 = blockIdx.x * BN;

    __shared__ float Ws[BKK][BM];
    __shared__ float Is[BKK][BN];

    const int tid = threadIdx.x;
    const int tx = tid & 15;
    const int ty = tid >> 4;

    float acc[4][8] = {};

    for (int k0 = 0; k0 < K; k0 += BKK) {
        #pragma unroll
        for (int i = 0; i < 4; i++) {
            int e = tid + i * 256;
            int m = e >> 4, k = e & 15;
            Ws[k][m] = Wt[(size_t)(m0 + m) * K + k0 + k];
        }
        #pragma unroll
        for (int i = 0; i < 2; i++) {
            int e = tid + i * 256;
            int k = e >> 5, n4 = e & 31;
            float4 v = *reinterpret_cast<const float4*>(
                &Ib[(size_t)(k0 + k) * N + n0 + n4 * 4]);
            *reinterpret_cast<float4*>(&Is[k][n4 * 4]) = v;
        }
        __syncthreads();
        #pragma unroll
        for (int k = 0; k < BKK; k++) {
            float4 av = *reinterpret_cast<const float4*>(&Ws[k][ty * 4]);
            float4 b0 = *reinterpret_cast<const float4*>(&Is[k][tx * 8]);
            float4 b1 = *reinterpret_cast<const float4*>(&Is[k][tx * 8 + 4]);
            float a[4] = {av.x, av.y, av.z, av.w};
            float bb[8] = {b0.x, b0.y, b0.z, b0.w, b1.x, b1.y, b1.z, b1.w};
            #pragma unroll
            for (int i = 0; i < 4; i++)
                #pragma unroll
                for (int j = 0; j < 8; j++)
                    acc[i][j] = fmaf(a[i], bb[j], acc[i][j]);
        }
        __syncthreads();
    }
    #pragma unroll
    for (int i = 0; i < 4; i++) {
        size_t row = (size_t)(m0 + ty * 4 + i) * N + n0 + tx * 8;
        *reinterpret_cast<float4*>(&Ob[row]) =
            make_float4(acc[i][0], acc[i][1], acc[i][2], acc[i][3]);
        *reinterpret_cast<float4*>(&Ob[row + 4]) =
            make_float4(acc[i][4], acc[i][5], acc[i][6], acc[i][7]);
    }
}

// ---- merged dual-branch strip conv + 3x3 dw, interior-specialized ----------
__global__ __launch_bounds__(256) void highpre4_kernel(
    const float* __restrict__ x,
    const float* __restrict__ w_dww, const float* __restrict__ b_dww,
    const float* __restrict__ w_dwh, const float* __restrict__ b_dwh,
    const float* __restrict__ w_dwhw, const float* __restrict__ b_dwhw)
{
    const int zc = blockIdx.z;               // b*192 + c
    const int b = zc / DIMC, c = zc % DIMC;
    const int y0 = blockIdx.y * 32, x0 = blockIdx.x * 32;
    const float* xp = x + (size_t)zc * HW;

    __shared__ float xs[44][48];
    __shared__ float sh[34][36];
    __shared__ float sv[34][36];
    __shared__ float wgt[40];

    const int tid = threadIdx.x;

    if (tid < 11)       wgt[tid] = w_dww[c * 11 + tid];
    else if (tid < 22)  wgt[tid] = w_dwh[c * 11 + tid - 11];
    else if (tid < 31)  wgt[tid] = w_dwhw[c * 9 + tid - 22];
    else if (tid < 40)  wgt[tid] = w_dwhw[(c + DIMC) * 9 + tid - 31];

    const bool interior = (blockIdx.x >= 1 && blockIdx.x <= 6 &&
                           blockIdx.y >= 1 && blockIdx.y <= 6);
    const float bhv = b_dww[c], bvv = b_dwh[c];

    if (interior) {
        for (int idx = tid; idx < 528; idx += 256) {
            int r = idx / 12, q = idx - r * 12;
            float4 v = *reinterpret_cast<const float4*>(
                xp + (size_t)(y0 - 6 + r) * WW + (x0 - 8) + (q << 2));
            *reinterpret_cast<float4*>(&xs[r][q << 2]) = v;
        }
        __syncthreads();

        for (int item = tid; item < 306; item += 256) {
            int r = item / 9, g = item - r * 9;
            int c0 = g << 2;
            float4 q0 = *reinterpret_cast<const float4*>(&xs[r + 5][c0]);
            float4 q1 = *reinterpret_cast<const float4*>(&xs[r + 5][c0 + 4]);
            float4 q2 = *reinterpret_cast<const float4*>(&xs[r + 5][c0 + 8]);
            float4 q3 = *reinterpret_cast<const float4*>(&xs[r + 5][c0 + 12]);
            float v[16] = {q0.x, q0.y, q0.z, q0.w, q1.x, q1.y, q1.z, q1.w,
                           q2.x, q2.y, q2.z, q2.w, q3.x, q3.y, q3.z, q3.w};
            #pragma unroll
            for (int jj = 0; jj < 4; jj++) {
                int cc = c0 + jj;
                if (cc < 34) {
                    float s = bhv;
                    #pragma unroll
                    for (int k = 0; k < 11; k++) s = fmaf(v[jj + 2 + k], wgt[k], s);
                    sh[r][cc] = s;
                }
            }
        }
        for (int item = tid; item < 306; item += 256) {
            int gi = item / 34, cc = item - gi * 34;
            int r0 = gi << 2;
            float v[14];
            #pragma unroll
            for (int k = 0; k < 14; k++) v[k] = xs[r0 + k][cc + 7];
            #pragma unroll
            for (int ii = 0; ii < 4; ii++) {
                int r = r0 + ii;
                if (r < 34) {
                    float s = bvv;
                    #pragma unroll
                    for (int k = 0; k < 11; k++) s = fmaf(v[ii + k], wgt[11 + k], s);
                    sv[r][cc] = s;
                }
            }
        }
    } else {
        {
            int r = tid / 44, cc = tid - r * 44;
            #pragma unroll
            for (int it = 0; it < 8; it++) {
                if (r < 44) {
                    int gy = y0 - 6 + r, gx = x0 - 6 + cc;
                    float v = 0.f;
                    if (gy >= 0 && gy < HH && gx >= 0 && gx < WW) v = xp[gy * WW + gx];
                    xs[r][cc] = v;
                }
                r += 5; cc += 36;
                if (cc >= 44) { cc -= 44; r += 1; }
            }
        }
        __syncthreads();

        for (int item = tid; item < 306; item += 256) {
            int r = item / 9, g = item - r * 9;
            int c0 = g << 2;
            float4 q0 = *reinterpret_cast<const float4*>(&xs[r + 5][c0]);
            float4 q1 = *reinterpret_cast<const float4*>(&xs[r + 5][c0 + 4]);
            float4 q2 = *reinterpret_cast<const float4*>(&xs[r + 5][c0 + 8]);
            float4 q3 = *reinterpret_cast<const float4*>(&xs[r + 5][c0 + 12]);
            float v[16] = {q0.x, q0.y, q0.z, q0.w, q1.x, q1.y, q1.z, q1.w,
                           q2.x, q2.y, q2.z, q2.w, q3.x, q3.y, q3.z, q3.w};
            int gy = y0 - 1 + r;
            bool rowok = (gy >= 0 && gy < HH);
            #pragma unroll
            for (int jj = 0; jj < 4; jj++) {
                int cc = c0 + jj;
                if (cc < 34) {
                    float s = bhv;
                    #pragma unroll
                    for (int k = 0; k < 11; k++) s = fmaf(v[jj + k], wgt[k], s);
                    int gx = x0 - 1 + cc;
                    sh[r][cc] = (rowok && gx >= 0 && gx < WW) ? s : 0.f;
                }
            }
        }
        for (int item = tid; item < 306; item += 256) {
            int gi = item / 34, cc = item - gi * 34;
            int r0 = gi << 2;
            float v[14];
            #pragma unroll
            for (int k = 0; k < 14; k++) v[k] = xs[r0 + k][cc + 5];
            int gx = x0 - 1 + cc;
            bool colok = (gx >= 0 && gx < WW);
            #pragma unroll
            for (int ii = 0; ii < 4; ii++) {
                int r = r0 + ii;
                if (r < 34) {
                    float s = bvv;
                    #pragma unroll
                    for (int k = 0; k < 11; k++) s = fmaf(v[ii + k], wgt[11 + k], s);
                    int gy = y0 - 1 + r;
                    sv[r][cc] = (colok && gy >= 0 && gy < HH) ? s : 0.f;
                }
            }
        }
    }
    __syncthreads();

    const float b3h = b_dwhw[c], b3v = b_dwhw[c + DIMC];
    float* oph = g_hcatdw + ((size_t)b * 384 + c) * HW;
    float* opv = g_hcatdw + ((size_t)b * 384 + DIMC + c) * HW;
    {
        int oy = tid >> 3, g = tid & 7;
        int c0 = g << 2;
        float hv[3][6], vv[3][6];
        #pragma unroll
        for (int ky = 0; ky < 3; ky++) {
            float4 a = *reinterpret_cast<const float4*>(&sh[oy + ky][c0]);
            float2 b2 = *reinterpret_cast<const float2*>(&sh[oy + ky][c0 + 4]);
            hv[ky][0] = a.x; hv[ky][1] = a.y; hv[ky][2] = a.z; hv[ky][3] = a.w;
            hv[ky][4] = b2.x; hv[ky][5] = b2.y;
            float4 av = *reinterpret_cast<const float4*>(&sv[oy + ky][c0]);
            float2 bv2 = *reinterpret_cast<const float2*>(&sv[oy + ky][c0 + 4]);
            vv[ky][0] = av.x; vv[ky][1] = av.y; vv[ky][2] = av.z; vv[ky][3] = av.w;
            vv[ky][4] = bv2.x; vv[ky][5] = bv2.y;
        }
        float r1[4], r2[4];
        #pragma unroll
        for (int jj = 0; jj < 4; jj++) {
            float s1 = b3h, s2 = b3v;
            #pragma unroll
            for (int ky = 0; ky < 3; ky++)
                #pragma unroll
                for (int kx = 0; kx < 3; kx++) {
                    s1 = fmaf(hv[ky][jj + kx], wgt[22 + ky * 3 + kx], s1);
                    s2 = fmaf(vv[ky][jj + kx], wgt[31 + ky * 3 + kx], s2);
                }
            r1[jj] = s1; r2[jj] = s2;
        }
        size_t o = (size_t)(y0 + oy) * WW + x0 + c0;
        *reinterpret_cast<float4*>(oph + o) = make_float4(r1[0], r1[1], r1[2], r1[3]);
        *reinterpret_cast<float4*>(opv + o) = make_float4(r2[0], r2[1], r2[2], r2[3]);
    }
}

// ----------------------------- avg pool 8x8 (float4) -------------------------
__global__ void pool_kernel(const float* __restrict__ x)
{
    int idx = blockIdx.x * 256 + threadIdx.x;
    if (idx >= BATCH * DIMC * PD) return;
    int p = idx % PD; int bc = idx / PD;
    int yd = p / WD, xd = p % WD;
    const float* xp = x + (size_t)bc * HW + (yd * 8) * WW + xd * 8;
    float s = 0.f;
    #pragma unroll
    for (int i = 0; i < 8; i++) {
        float4 a = *reinterpret_cast<const float4*>(xp + i * WW);
        float4 bq = *reinterpret_cast<const float4*>(xp + i * WW + 4);
        s += (a.x + a.y + a.z + a.w) + (bq.x + bq.y + bq.z + bq.w);
    }
    g_xdown[idx] = s * (1.f / 64.f);
}

// ------------------------- 3x3 depthwise (32x32) ----------------------------
__global__ __launch_bounds__(256) void dw3x3_small_kernel(const float* __restrict__ w)
{
    const int zc = blockIdx.x;
    const int c = zc % 576;
    __shared__ float xs[34][34];
    __shared__ float w3[9];
    const int tid = threadIdx.x;
    const float* ip = g_qkv + (size_t)zc * PD;
    if (tid < 9) w3[tid] = w[c * 9 + tid];
    for (int i = tid; i < 34 * 34; i += 256) {
        int r = i / 34, cc = i % 34;
        int gy = r - 1, gx = cc - 1;
        xs[r][cc] = (gy >= 0 && gy < HD && gx >= 0 && gx < WD) ? ip[gy * WD + gx] : 0.f;
    }
    __syncthreads();
    const int tx = tid & 31, ty = tid >> 5;
    float* op = g_qkvdw + (size_t)zc * PD;
    #pragma unroll
    for (int rr = 0; rr < 4; rr++) {
        int oy = ty + rr * 8;
        float s = 0.f;
        #pragma unroll
        for (int ky = 0; ky < 3; ky++)
            #pragma unroll
            for (int kx = 0; kx < 3; kx++)
                s = fmaf(xs[oy + ky][tx + kx], w3[ky * 3 + kx], s);
        op[oy * WD + tx] = s;
    }
}

// --------------- attention Gram + softmax (coalesced, chunked) --------------
__global__ void attn_kernel2(const float* __restrict__ temp)
{
    const int bh = blockIdx.x;
    const int b = bh / HEADS, h = bh % HEADS;
    const float* q = g_qkvdw + ((size_t)b * 576 + h * CH) * PD;
    const float* kk = g_qkvdw + ((size_t)b * 576 + DIMC + h * CH) * PD;

    __shared__ float qs[CH][65], ks[CH][65];
    __shared__ float qn[CH], kn[CH], sm[CH][CH];
    const int tid = threadIdx.x;            // 576
    const int c = tid / CH, d = tid % CH;

    float acc = 0.f, accq = 0.f, acck = 0.f;
    for (int chn = 0; chn < 16; chn++) {
        #pragma unroll
        for (int i = 0; i < 3; i++) {
            int e = tid + i * 576;
            if (e < CH * 64) {
                int r = e >> 6, cc = e & 63;
                qs[r][cc] = q[(size_t)r * PD + chn * 64 + cc];
                ks[r][cc] = kk[(size_t)r * PD + chn * 64 + cc];
            }
        }
        __syncthreads();
        #pragma unroll 8
        for (int i = 0; i < 64; i++)
            acc = fmaf(qs[c][i], ks[d][i], acc);
        if (c == d) {
            #pragma unroll 8
            for (int i = 0; i < 64; i++) {
                accq = fmaf(qs[c][i], qs[c][i], accq);
                acck = fmaf(ks[c][i], ks[c][i], acck);
            }
        }
        __syncthreads();
    }
    if (c == d) {
        qn[c] = fmaxf(sqrtf(accq), 1e-12f);
        kn[c] = fmaxf(sqrtf(acck), 1e-12f);
    }
    __syncthreads();
    sm[c][d] = acc / (qn[c] * kn[d]) * temp[h];
    __syncthreads();
    if (tid < CH) {
        float m = -1e30f;
        for (int j = 0; j < CH; j++) m = fmaxf(m, sm[tid][j]);
        float e[CH]; float ssum = 0.f;
        for (int j = 0; j < CH; j++) { e[j] = expf(sm[tid][j] - m); ssum += e[j]; }
        float inv = 1.f / ssum;
        for (int j = 0; j < CH; j++)
            g_attn[((size_t)bh * CH + tid) * CH + j] = e[j] * inv;
    }
}

// ------------------------------ v gate (coalesced) ---------------------------
__global__ void vgate_kernel2(const float* __restrict__ w2, const float* __restrict__ w3)
{
    const int b = blockIdx.x;
    const float* v = g_qkvdw + ((size_t)b * 576 + 2 * DIMC) * PD;
    __shared__ float vmax[DIMC], vavg[DIMC];
    const int tid = threadIdx.x;   // 256
    const int wid = tid >> 5, lane = tid & 31;
    for (int c = wid; c < DIMC; c += 8) {
        const float* p = v + (size_t)c * PD;
        float m = -1e30f, s = 0.f;
        for (int i = lane; i < PD; i += 32) { float vv = p[i]; m = fmaxf(m, vv); s += vv; }
        #pragma unroll
        for (int off = 16; off; off >>= 1) {
            m = fmaxf(m, __shfl_xor_sync(0xFFFFFFFF, m, off));
            s += __shfl_xor_sync(0xFFFFFFFF, s, off);
        }
        if (lane == 0) { vmax[c] = m; vavg[c] = s * (1.f / (float)PD); }
    }
    __syncthreads();
    if (tid < DIMC) {
        float g = 0.f;
        for (int c = 0; c < DIMC; c++)
            g = fmaf(w2[tid * DIMC + c], vmax[c], fmaf(w3[tid * DIMC + c], vavg[c], g));
        g_gate[b * DIMC + tid] = g;
    }
}

// -------- fused dw3x3(conv4b)*gate + attention apply -> cat[192:384) ---------
__global__ __launch_bounds__(256) void dwattn2_kernel(const float* __restrict__ w4b)
{
    const int z = blockIdx.z;
    const int b = z >> 3, h = z & 7;
    const int x0 = blockIdx.x * 32, y0 = blockIdx.y * 8;
    const int tid = threadIdx.x;

    __shared__ float xs[CH][10][36];
    __shared__ float a2[CH][CH];
    __shared__ float w3s[CH][9];

    const bool interior = (blockIdx.x >= 1 && blockIdx.x <= 6 &&
                           blockIdx.y >= 1 && blockIdx.y <= 30);

    const float* tb = g_t4 + ((size_t)b * DIMC + h * CH) * HW;
    {
        int d = tid / 340, rem = tid - d * 340;
        int r = rem / 34, cx = rem - r * 34;
        if (interior) {
            for (int i = tid; i < 8160; i += 256) {
                xs[d][r][cx] = tb[(size_t)d * HW + (size_t)(y0 - 1 + r) * WW + x0 - 1 + cx];
                cx += 18; r += 7;
                if (cx >= 34) { cx -= 34; r += 1; }
                if (r >= 10) { r -= 10; d += 1; }
            }
        } else {
            for (int i = tid; i < 8160; i += 256) {
                int gy = y0 - 1 + r, gx = x0 - 1 + cx;
                float v = 0.f;
                if (gy >= 0 && gy < HH && gx >= 0 && gx < WW)
                    v = tb[(size_t)d * HW + (size_t)gy * WW + gx];
                xs[d][r][cx] = v;
                cx += 18; r += 7;
                if (cx >= 34) { cx -= 34; r += 1; }
                if (r >= 10) { r -= 10; d += 1; }
            }
        }
    }
    if (tid < CH * 9) {
        int d = tid / 9;
        w3s[d][tid % 9] = w4b[(h * CH + d) * 9 + tid % 9];
    }
    for (int i = tid; i < CH * CH; i += 256) {
        int c = i / CH, d = i % CH;
        a2[c][d] = g_attn[((size_t)(b * HEADS + h) * CH + c) * CH + d] *
                   g_gate[b * DIMC + h * CH + d];
    }
    __syncthreads();

    const int tx = tid & 31, ty = tid >> 5;
    float dw[CH];
    #pragma unroll
    for (int d = 0; d < CH; d++) {
        float s = 0.f;
        #pragma unroll
        for (int ky = 0; ky < 3; ky++)
            #pragma unroll
            for (int kx = 0; kx < 3; kx++)
                s = fmaf(xs[d][ty + ky][tx + kx], w3s[d][ky * 3 + kx], s);
        dw[d] = s;
    }
    float* ob = g_cat + ((size_t)b * 384 + DIMC + h * CH) * HW + (y0 + ty) * WW + x0 + tx;
    #pragma unroll
    for (int c = 0; c < CH; c++) {
        float s = 0.f;
        #pragma unroll
        for (int d = 0; d < CH; d++) s = fmaf(a2[c][d], dw[d], s);
        ob[(size_t)c * HW] = s;
    }
}

// ------------------------------- launch -------------------------------------
extern "C" void kernel_launch(void* const* d_in, const int* in_sizes, int n_in,
                              void* d_out, int out_size)
{
    const float* x        = (const float*)d_in[0];
    const float* w_dww    = (const float*)d_in[1];
    const float* b_dww    = (const float*)d_in[2];
    const float* w_dwh    = (const float*)d_in[3];
    const float* b_dwh    = (const float*)d_in[4];
    const float* w_dwhw   = (const float*)d_in[5];
    const float* b_dwhw   = (const float*)d_in[6];
    const float* w_conv1  = (const float*)d_in[7];
    const float* w_qkv    = (const float*)d_in[8];
    const float* w_qkvdw  = (const float*)d_in[9];
    const float* w_conv2  = (const float*)d_in[10];
    const float* w_conv3  = (const float*)d_in[11];
    const float* w_conv4a = (const float*)d_in[12];
    const float* w_conv4b = (const float*)d_in[13];
    const float* w_proj   = (const float*)d_in[14];
    const float* temp     = (const float*)d_in[15];
    float* out = (float*)d_out;

    float *p_hcatdw, *p_cat, *p_t4, *p_xdown, *p_qkv;
    __nv_bfloat16 *p_w1h, *p_w1l, *p_w4h, *p_w4l, *p_wph, *p_wpl;
    cudaGetSymbolAddress((void**)&p_hcatdw, g_hcatdw);
    cudaGetSymbolAddress((void**)&p_cat,    g_cat);
    cudaGetSymbolAddress((void**)&p_t4,     g_t4);
    cudaGetSymbolAddress((void**)&p_xdown,  g_xdown);
    cudaGetSymbolAddress((void**)&p_qkv,    g_qkv);
    cudaGetSymbolAddress((void**)&p_w1h,    g_w1h);
    cudaGetSymbolAddress((void**)&p_w1l,    g_w1l);
    cudaGetSymbolAddress((void**)&p_w4h,    g_w4h);
    cudaGetSymbolAddress((void**)&p_w4l,    g_w4l);
    cudaGetSymbolAddress((void**)&p_wph,    g_wph);
    cudaGetSymbolAddress((void**)&p_wpl,    g_wpl);

    cudaFuncSetAttribute(fgemm_kernel,
                         cudaFuncAttributeMaxDynamicSharedMemorySize, SMEMT);

    // weight splits
    convw_kernel<<<(192 * 384 + 255) / 256, 256>>>(w_conv1, p_w1h, p_w1l, 192 * 384);
    convw_kernel<<<(192 * 192 + 255) / 256, 256>>>(w_conv4a, p_w4h, p_w4l, 192 * 192);
    convw_kernel<<<(192 * 384 + 255) / 256, 256>>>(w_proj, p_wph, p_wpl, 192 * 384);

    // merged + interior-specialized high-branch depthwise stack
    highpre4_kernel<<<dim3(WW / 32, HH / 32, BATCH * DIMC), 256>>>(
        x, w_dww, b_dww, w_dwh, b_dwh, w_dwhw, b_dwhw);

    // pool
    pool_kernel<<<(BATCH * DIMC * PD + 255) / 256, 256>>>(x);

    // conv1: cat[:,0:192) = W1 @ hcatdw
    fgemm_kernel<<<dim3(HW / 128, 1, BATCH), 256, SMEMT>>>(
        p_hcatdw, 384, p_w1h, p_w1l, p_cat, 384, 0);

    // low branch
    gemm_kernel<<<dim3(PD / BN, 576 / BM, BATCH), 256>>>(
        w_qkv, p_xdown, p_qkv, DIMC, PD, (size_t)DIMC * PD, (size_t)576 * PD);
    dw3x3_small_kernel<<<BATCH * 576, 256>>>(w_qkvdw);
    attn_kernel2<<<BATCH * HEADS, 576>>>(temp);
    vgate_kernel2<<<BATCH, 256>>>(w_conv2, w_conv3);

    // conv4a: t4 = W4a @ x
    fgemm_kernel<<<dim3(HW / 128, 1, BATCH), 256, SMEMT>>>(
        x, DIMC, p_w4h, p_w4l, p_t4, DIMC, 0);

    // fused dw(conv4b)*gate + attn apply -> cat[:,192:384)
    dwattn2_kernel<<<dim3(WW / 32, HH / 8, BATCH * HEADS), 256>>>(w_conv4b);

    // proj: out = Wp @ cat
    fgemm_kernel<<<dim3(HW / 128, 1, BATCH), 256, SMEMT>>>(
        p_cat, 384, p_wph, p_wpl, out, DIMC, 0);
}

// round 15
// speedup vs baseline: 1.0209x; 1.0209x over previous
#include <cuda_runtime.h>
#include <cuda_bf16.h>
#include <cstdint>

// ---------------------------------------------------------------------------
// HybridAttention — round 13: fgemm reverted to R11 tiling (K-chunk 64) with
// mt-interleaved mma order (same-accumulator issue distance 2 -> 4).
// Rest identical to passing R11 kernel (1618.9 us).
// ---------------------------------------------------------------------------

#define DIMC   192
#define HEADS  8
#define CH     24
#define HH     256
#define WW     256
#define HW     65536
#define HD     32
#define WD     32
#define PD     1024
#define BATCH  4

// ------------------------- scratch (static device) -------------------------
__device__ float g_hcatdw[(size_t)BATCH * 384 * HW];
__device__ float g_cat   [(size_t)BATCH * 384 * HW];
__device__ float g_t4    [(size_t)BATCH * DIMC * HW];
__device__ float g_xdown [(size_t)BATCH * DIMC * PD];
__device__ float g_qkv   [(size_t)BATCH * 576 * PD];
__device__ float g_qkvdw [(size_t)BATCH * 576 * PD];
__device__ float g_attn  [(size_t)BATCH * HEADS * CH * CH];
__device__ float g_gate  [(size_t)BATCH * DIMC];
__device__ __nv_bfloat16 g_w1h[192 * 384], g_w1l[192 * 384];
__device__ __nv_bfloat16 g_w4h[192 * 192], g_w4l[192 * 192];
__device__ __nv_bfloat16 g_wph[192 * 384], g_wpl[192 * 384];

// --------------------------- ptx helpers (sm_80 ISA) ------------------------
__device__ __forceinline__ uint32_t smem_u32(const void* p) {
    uint32_t a;
    asm("{ .reg .u64 t; cvta.to.shared.u64 t, %1; cvt.u32.u64 %0, t; }"
        : "=r"(a) : "l"(p));
    return a;
}
__device__ __forceinline__ void cpasync16(uint32_t saddr, const void* gaddr) {
    asm volatile("cp.async.cg.shared.global [%0], [%1], 16;"
                 :: "r"(saddr), "l"(gaddr));
}
__device__ __forceinline__ void cpcommit() {
    asm volatile("cp.async.commit_group;" ::: "memory");
}
template<int N> __device__ __forceinline__ void cpwait() {
    asm volatile("cp.async.wait_group %0;" :: "n"(N) : "memory");
}
__device__ __forceinline__ void ldsm4(uint32_t* r, uint32_t addr) {
    asm volatile("ldmatrix.sync.aligned.m8n8.x4.shared.b16 {%0,%1,%2,%3}, [%4];"
        : "=r"(r[0]), "=r"(r[1]), "=r"(r[2]), "=r"(r[3]) : "r"(addr));
}
__device__ __forceinline__ void ldsm4t(uint32_t* r, uint32_t addr) {
    asm volatile("ldmatrix.sync.aligned.m8n8.x4.trans.shared.b16 {%0,%1,%2,%3}, [%4];"
        : "=r"(r[0]), "=r"(r[1]), "=r"(r[2]), "=r"(r[3]) : "r"(addr));
}
__device__ __forceinline__ void mma16816(float* d, const uint32_t* a,
                                         uint32_t b0, uint32_t b1) {
    asm volatile(
        "mma.sync.aligned.m16n8k16.row.col.f32.bf16.bf16.f32 "
        "{%0,%1,%2,%3}, {%4,%5,%6,%7}, {%8,%9}, {%0,%1,%2,%3};"
        : "+f"(d[0]), "+f"(d[1]), "+f"(d[2]), "+f"(d[3])
        : "r"(a[0]), "r"(a[1]), "r"(a[2]), "r"(a[3]), "r"(b0), "r"(b1));
}
__device__ __forceinline__ uint32_t pk2(float a, float b) {
    __nv_bfloat162 t; t.x = __float2bfloat16(a); t.y = __float2bfloat16(b);
    return *reinterpret_cast<uint32_t*>(&t);
}

// ------------------------------ MMA-GEMM (K-chunk 64, R11 tiling) -----------
#define ASTR  272      // 128 px bf16 = 256B + 16 pad
#define BSTR  144      // 64 k bf16 = 128B + 16 pad
#define ATH   0
#define ATL   17408    // 64*272
#define BH    34816
#define BL    62464    // +192*144
#define SMEM1 90112
#define SMEMT (2 * SMEM1)

__device__ __forceinline__ void lda_regs(float4* r, const float* Ab, int k0, int tid) {
    #pragma unroll
    for (int i = 0; i < 8; i++) {
        int e = tid + (i << 8); int k = e >> 5, q = e & 31;
        r[i] = *reinterpret_cast<const float4*>(Ab + (size_t)(k0 + k) * HW + (q << 2));
    }
}
__device__ __forceinline__ void cvt_sts(const float4* r, char* smem,
                                        uint32_t bufOff, int tid) {
    #pragma unroll
    for (int i = 0; i < 8; i++) {
        int e = tid + (i << 8); int k = e >> 5, q = e & 31;
        float4 f = r[i];
        uint32_t so = bufOff + (uint32_t)k * ASTR + (q << 3);
        uint2 hv, lv;
        hv.x = pk2(f.x, f.y); hv.y = pk2(f.z, f.w);
        float rx = f.x - __bfloat162float(__float2bfloat16(f.x));
        float ry = f.y - __bfloat162float(__float2bfloat16(f.y));
        float rz = f.z - __bfloat162float(__float2bfloat16(f.z));
        float rw = f.w - __bfloat162float(__float2bfloat16(f.w));
        lv.x = pk2(rx, ry); lv.y = pk2(rz, rw);
        *reinterpret_cast<uint2*>(smem + so + ATH) = hv;
        *reinterpret_cast<uint2*>(smem + so + ATL - ATH) = lv;
    }
}
__device__ __forceinline__ void ldb_async(uint32_t sbuf,
    const __nv_bfloat16* Wh, const __nv_bfloat16* Wl, int Ka, int k0, int tid) {
    #pragma unroll
    for (int i = 0; i < 6; i++) {
        int e = tid + (i << 8); int r = e >> 3, q = e & 7;
        size_t go = (size_t)r * Ka + k0 + (q << 3);
        uint32_t so = r * BSTR + (q << 4);
        cpasync16(sbuf + BH + so, Wh + go);
        cpasync16(sbuf + BL + so, Wl + go);
    }
}

__global__ __launch_bounds__(256, 1) void fgemm_kernel(
    const float* __restrict__ In, int Ka,
    const __nv_bfloat16* __restrict__ Whi, const __nv_bfloat16* __restrict__ Wlo,
    float* __restrict__ Out, int chTot, int outOff)
{
    extern __shared__ char smem[];
    const uint32_t sb = smem_u32(smem);
    const int tid = threadIdx.x;
    const int warp = tid >> 5, lane = tid & 31;
    const int mw = warp >> 1, nw = warp & 1;        // 4 (M) x 2 (N) warps
    const int b = blockIdx.z;
    const int px0 = blockIdx.x * 128;
    const int nChunks = Ka >> 6;

    const float* Ab = In + (size_t)b * Ka * HW + px0;

    float acc[2][12][4] = {};

    const int grp = lane >> 3, rr = lane & 7;
    uint32_t aoff[2];
    #pragma unroll
    for (int mt = 0; mt < 2; mt++)
        aoff[mt] = (uint32_t)((grp >> 1) * 8 + rr) * ASTR +
                   (uint32_t)(mw * 32 + mt * 16 + (grp & 1) * 8) * 2;
    const uint32_t boff = (uint32_t)(nw * 96 + rr + (grp >> 1) * 8) * BSTR +
                          (grp & 1) * 16;

    float4 ar[8];
    lda_regs(ar, Ab, 0, tid);
    ldb_async(sb, Whi, Wlo, Ka, 0, tid);
    cpcommit();

    for (int ch = 0; ch < nChunks; ch++) {
        const uint32_t bufo = (uint32_t)(ch & 1) * SMEM1;
        cvt_sts(ar, smem + bufo, ATH, tid);
        if (ch + 1 < nChunks) {
            lda_regs(ar, Ab, (ch + 1) << 6, tid);
            ldb_async(sb + ((ch + 1) & 1) * SMEM1, Whi, Wlo, Ka, (ch + 1) << 6, tid);
            cpcommit();
            cpwait<1>();
        } else {
            cpwait<0>();
        }
        __syncthreads();

        const uint32_t buf = sb + bufo;
        #pragma unroll
        for (int ks = 0; ks < 4; ks++) {
            uint32_t ah[2][4], al[2][4];
            ldsm4t(ah[0], buf + ATH + aoff[0] + ks * (16 * ASTR));
            ldsm4t(ah[1], buf + ATH + aoff[1] + ks * (16 * ASTR));
            ldsm4t(al[0], buf + ATL + aoff[0] + ks * (16 * ASTR));
            ldsm4t(al[1], buf + ATL + aoff[1] + ks * (16 * ASTR));
            #pragma unroll
            for (int p = 0; p < 6; p++) {
                uint32_t bh[4], bl[4];
                uint32_t ba = buf + boff + (uint32_t)p * 16 * BSTR + ks * 32;
                ldsm4(bh, ba + BH);
                ldsm4(bl, ba + BL);
                // mt-interleaved: same-acc issue distance 4 (was 2)
                mma16816(acc[0][2 * p],     ah[0], bh[0], bh[1]);
                mma16816(acc[1][2 * p],     ah[1], bh[0], bh[1]);
                mma16816(acc[0][2 * p + 1], ah[0], bh[2], bh[3]);
                mma16816(acc[1][2 * p + 1], ah[1], bh[2], bh[3]);
                mma16816(acc[0][2 * p],     ah[0], bl[0], bl[1]);
                mma16816(acc[1][2 * p],     ah[1], bl[0], bl[1]);
                mma16816(acc[0][2 * p + 1], ah[0], bl[2], bl[3]);
                mma16816(acc[1][2 * p + 1], ah[1], bl[2], bl[3]);
                mma16816(acc[0][2 * p],     al[0], bh[0], bh[1]);
                mma16816(acc[1][2 * p],     al[1], bh[0], bh[1]);
                mma16816(acc[0][2 * p + 1], al[0], bh[2], bh[3]);
                mma16816(acc[1][2 * p + 1], al[1], bh[2], bh[3]);
            }
        }
        __syncthreads();
    }

    // ---- epilogue: fp32 ch-major ----
    const int mrow = lane >> 2;
    const int ncol = 2 * (lane & 3);
    float* ob = Out + ((size_t)b * chTot + outOff) * HW + px0;
    #pragma unroll
    for (int mt = 0; mt < 2; mt++) {
        #pragma unroll
        for (int nt = 0; nt < 12; nt++) {
            int m = mw * 32 + mt * 16 + mrow;
            int n = nw * 96 + nt * 8 + ncol;
            ob[(size_t)n * HW + m]           = acc[mt][nt][0];
            ob[(size_t)(n + 1) * HW + m]     = acc[mt][nt][1];
            ob[(size_t)n * HW + m + 8]       = acc[mt][nt][2];
            ob[(size_t)(n + 1) * HW + m + 8] = acc[mt][nt][3];
        }
    }
}

// ----------------------- weight convert (hi/lo) -----------------------------
__global__ void convw_kernel(const float* __restrict__ w,
                             __nv_bfloat16* __restrict__ hi,
                             __nv_bfloat16* __restrict__ lo, int n)
{
    int i = blockIdx.x * 256 + threadIdx.x;
    if (i >= n) return;
    float v = w[i];
    __nv_bfloat16 h = __float2bfloat16(v);
    hi[i] = h;
    lo[i] = __float2bfloat16(v - __bfloat162float(h));
}

// ------------------------------ fp32 SGEMM (qkv only) ------------------------
#define BM 64
#define BN 128
#define BKK 16

__global__ __launch_bounds__(256) void gemm_kernel(
    const float* __restrict__ Wt, const float* __restrict__ In,
    float* __restrict__ Out, int K, int N, size_t inBS, size_t outBS)
{
    const int b = blockIdx.z;
    const float* Ib = In + (size_t)b * inBS;
    float* Ob = Out + (size_t)b * outBS;
    const int m0 = blockIdx.y * BM;
    const int n0 = blockIdx.x * BN;

    __shared__ float Ws[BKK][BM];
    __shared__ float Is[BKK][BN];

    const int tid = threadIdx.x;
    const int tx = tid & 15;
    const int ty = tid >> 4;

    float acc[4][8] = {};

    for (int k0 = 0; k0 < K; k0 += BKK) {
        #pragma unroll
        for (int i = 0; i < 4; i++) {
            int e = tid + i * 256;
            int m = e >> 4, k = e & 15;
            Ws[k][m] = Wt[(size_t)(m0 + m) * K + k0 + k];
        }
        #pragma unroll
        for (int i = 0; i < 2; i++) {
            int e = tid + i * 256;
            int k = e >> 5, n4 = e & 31;
            float4 v = *reinterpret_cast<const float4*>(
                &Ib[(size_t)(k0 + k) * N + n0 + n4 * 4]);
            *reinterpret_cast<float4*>(&Is[k][n4 * 4]) = v;
        }
        __syncthreads();
        #pragma unroll
        for (int k = 0; k < BKK; k++) {
            float4 av = *reinterpret_cast<const float4*>(&Ws[k][ty * 4]);
            float4 b0 = *reinterpret_cast<const float4*>(&Is[k][tx * 8]);
            float4 b1 = *reinterpret_cast<const float4*>(&Is[k][tx * 8 + 4]);
            float a[4] = {av.x, av.y, av.z, av.w};
            float bb[8] = {b0.x, b0.y, b0.z, b0.w, b1.x, b1.y, b1.z, b1.w};
            #pragma unroll
            for (int i = 0; i < 4; i++)
                #pragma unroll
                for (int j = 0; j < 8; j++)
                    acc[i][j] = fmaf(a[i], bb[j], acc[i][j]);
        }
        __syncthreads();
    }
    #pragma unroll
    for (int i = 0; i < 4; i++) {
        size_t row = (size_t)(m0 + ty * 4 + i) * N + n0 + tx * 8;
        *reinterpret_cast<float4*>(&Ob[row]) =
            make_float4(acc[i][0], acc[i][1], acc[i][2], acc[i][3]);
        *reinterpret_cast<float4*>(&Ob[row + 4]) =
            make_float4(acc[i][4], acc[i][5], acc[i][6], acc[i][7]);
    }
}

// ---- merged dual-branch strip conv + 3x3 dw, interior-specialized ----------
__global__ __launch_bounds__(256) void highpre4_kernel(
    const float* __restrict__ x,
    const float* __restrict__ w_dww, const float* __restrict__ b_dww,
    const float* __restrict__ w_dwh, const float* __restrict__ b_dwh,
    const float* __restrict__ w_dwhw, const float* __restrict__ b_dwhw)
{
    const int zc = blockIdx.z;               // b*192 + c
    const int b = zc / DIMC, c = zc % DIMC;
    const int y0 = blockIdx.y * 32, x0 = blockIdx.x * 32;
    const float* xp = x + (size_t)zc * HW;

    __shared__ float xs[44][48];
    __shared__ float sh[34][36];
    __shared__ float sv[34][36];
    __shared__ float wgt[40];

    const int tid = threadIdx.x;

    if (tid < 11)       wgt[tid] = w_dww[c * 11 + tid];
    else if (tid < 22)  wgt[tid] = w_dwh[c * 11 + tid - 11];
    else if (tid < 31)  wgt[tid] = w_dwhw[c * 9 + tid - 22];
    else if (tid < 40)  wgt[tid] = w_dwhw[(c + DIMC) * 9 + tid - 31];

    const bool interior = (blockIdx.x >= 1 && blockIdx.x <= 6 &&
                           blockIdx.y >= 1 && blockIdx.y <= 6);
    const float bhv = b_dww[c], bvv = b_dwh[c];

    if (interior) {
        for (int idx = tid; idx < 528; idx += 256) {
            int r = idx / 12, q = idx - r * 12;
            float4 v = *reinterpret_cast<const float4*>(
                xp + (size_t)(y0 - 6 + r) * WW + (x0 - 8) + (q << 2));
            *reinterpret_cast<float4*>(&xs[r][q << 2]) = v;
        }
        __syncthreads();

        for (int item = tid; item < 306; item += 256) {
            int r = item / 9, g = item - r * 9;
            int c0 = g << 2;
            float4 q0 = *reinterpret_cast<const float4*>(&xs[r + 5][c0]);
            float4 q1 = *reinterpret_cast<const float4*>(&xs[r + 5][c0 + 4]);
            float4 q2 = *reinterpret_cast<const float4*>(&xs[r + 5][c0 + 8]);
            float4 q3 = *reinterpret_cast<const float4*>(&xs[r + 5][c0 + 12]);
            float v[16] = {q0.x, q0.y, q0.z, q0.w, q1.x, q1.y, q1.z, q1.w,
                           q2.x, q2.y, q2.z, q2.w, q3.x, q3.y, q3.z, q3.w};
            #pragma unroll
            for (int jj = 0; jj < 4; jj++) {
                int cc = c0 + jj;
                if (cc < 34) {
                    float s = bhv;
                    #pragma unroll
                    for (int k = 0; k < 11; k++) s = fmaf(v[jj + 2 + k], wgt[k], s);
                    sh[r][cc] = s;
                }
            }
        }
        for (int item = tid; item < 306; item += 256) {
            int gi = item / 34, cc = item - gi * 34;
            int r0 = gi << 2;
            float v[14];
            #pragma unroll
            for (int k = 0; k < 14; k++) v[k] = xs[r0 + k][cc + 7];
            #pragma unroll
            for (int ii = 0; ii < 4; ii++) {
                int r = r0 + ii;
                if (r < 34) {
                    float s = bvv;
                    #pragma unroll
                    for (int k = 0; k < 11; k++) s = fmaf(v[ii + k], wgt[11 + k], s);
                    sv[r][cc] = s;
                }
            }
        }
    } else {
        {
            int r = tid / 44, cc = tid - r * 44;
            #pragma unroll
            for (int it = 0; it < 8; it++) {
                if (r < 44) {
                    int gy = y0 - 6 + r, gx = x0 - 6 + cc;
                    float v = 0.f;
                    if (gy >= 0 && gy < HH && gx >= 0 && gx < WW) v = xp[gy * WW + gx];
                    xs[r][cc] = v;
                }
                r += 5; cc += 36;
                if (cc >= 44) { cc -= 44; r += 1; }
            }
        }
        __syncthreads();

        for (int item = tid; item < 306; item += 256) {
            int r = item / 9, g = item - r * 9;
            int c0 = g << 2;
            float4 q0 = *reinterpret_cast<const float4*>(&xs[r + 5][c0]);
            float4 q1 = *reinterpret_cast<const float4*>(&xs[r + 5][c0 + 4]);
            float4 q2 = *reinterpret_cast<const float4*>(&xs[r + 5][c0 + 8]);
            float4 q3 = *reinterpret_cast<const float4*>(&xs[r + 5][c0 + 12]);
            float v[16] = {q0.x, q0.y, q0.z, q0.w, q1.x, q1.y, q1.z, q1.w,
                           q2.x, q2.y, q2.z, q2.w, q3.x, q3.y, q3.z, q3.w};
            int gy = y0 - 1 + r;
            bool rowok = (gy >= 0 && gy < HH);
            #pragma unroll
            for (int jj = 0; jj < 4; jj++) {
                int cc = c0 + jj;
                if (cc < 34) {
                    float s = bhv;
                    #pragma unroll
                    for (int k = 0; k < 11; k++) s = fmaf(v[jj + k], wgt[k], s);
                    int gx = x0 - 1 + cc;
                    sh[r][cc] = (rowok && gx >= 0 && gx < WW) ? s : 0.f;
                }
            }
        }
        for (int item = tid; item < 306; item += 256) {
            int gi = item / 34, cc = item - gi * 34;
            int r0 = gi << 2;
            float v[14];
            #pragma unroll
            for (int k = 0; k < 14; k++) v[k] = xs[r0 + k][cc + 5];
            int gx = x0 - 1 + cc;
            bool colok = (gx >= 0 && gx < WW);
            #pragma unroll
            for (int ii = 0; ii < 4; ii++) {
                int r = r0 + ii;
                if (r < 34) {
                    float s = bvv;
                    #pragma unroll
                    for (int k = 0; k < 11; k++) s = fmaf(v[ii + k], wgt[11 + k], s);
                    int gy = y0 - 1 + r;
                    sv[r][cc] = (colok && gy >= 0 && gy < HH) ? s : 0.f;
                }
            }
        }
    }
    __syncthreads();

    const float b3h = b_dwhw[c], b3v = b_dwhw[c + DIMC];
    float* oph = g_hcatdw + ((size_t)b * 384 + c) * HW;
    float* opv = g_hcatdw + ((size_t)b * 384 + DIMC + c) * HW;
    {
        int oy = tid >> 3, g = tid & 7;
        int c0 = g << 2;
        float hv[3][6], vv[3][6];
        #pragma unroll
        for (int ky = 0; ky < 3; ky++) {
            float4 a = *reinterpret_cast<const float4*>(&sh[oy + ky][c0]);
            float2 b2 = *reinterpret_cast<const float2*>(&sh[oy + ky][c0 + 4]);
            hv[ky][0] = a.x; hv[ky][1] = a.y; hv[ky][2] = a.z; hv[ky][3] = a.w;
            hv[ky][4] = b2.x; hv[ky][5] = b2.y;
            float4 av = *reinterpret_cast<const float4*>(&sv[oy + ky][c0]);
            float2 bv2 = *reinterpret_cast<const float2*>(&sv[oy + ky][c0 + 4]);
            vv[ky][0] = av.x; vv[ky][1] = av.y; vv[ky][2] = av.z; vv[ky][3] = av.w;
            vv[ky][4] = bv2.x; vv[ky][5] = bv2.y;
        }
        float r1[4], r2[4];
        #pragma unroll
        for (int jj = 0; jj < 4; jj++) {
            float s1 = b3h, s2 = b3v;
            #pragma unroll
            for (int ky = 0; ky < 3; ky++)
                #pragma unroll
                for (int kx = 0; kx < 3; kx++) {
                    s1 = fmaf(hv[ky][jj + kx], wgt[22 + ky * 3 + kx], s1);
                    s2 = fmaf(vv[ky][jj + kx], wgt[31 + ky * 3 + kx], s2);
                }
            r1[jj] = s1; r2[jj] = s2;
        }
        size_t o = (size_t)(y0 + oy) * WW + x0 + c0;
        *reinterpret_cast<float4*>(oph + o) = make_float4(r1[0], r1[1], r1[2], r1[3]);
        *reinterpret_cast<float4*>(opv + o) = make_float4(r2[0], r2[1], r2[2], r2[3]);
    }
}

// ----------------------------- avg pool 8x8 (float4) -------------------------
__global__ void pool_kernel(const float* __restrict__ x)
{
    int idx = blockIdx.x * 256 + threadIdx.x;
    if (idx >= BATCH * DIMC * PD) return;
    int p = idx % PD; int bc = idx / PD;
    int yd = p / WD, xd = p % WD;
    const float* xp = x + (size_t)bc * HW + (yd * 8) * WW + xd * 8;
    float s = 0.f;
    #pragma unroll
    for (int i = 0; i < 8; i++) {
        float4 a = *reinterpret_cast<const float4*>(xp + i * WW);
        float4 bq = *reinterpret_cast<const float4*>(xp + i * WW + 4);
        s += (a.x + a.y + a.z + a.w) + (bq.x + bq.y + bq.z + bq.w);
    }
    g_xdown[idx] = s * (1.f / 64.f);
}

// ------------------------- 3x3 depthwise (32x32) ----------------------------
__global__ __launch_bounds__(256) void dw3x3_small_kernel(const float* __restrict__ w)
{
    const int zc = blockIdx.x;
    const int c = zc % 576;
    __shared__ float xs[34][34];
    __shared__ float w3[9];
    const int tid = threadIdx.x;
    const float* ip = g_qkv + (size_t)zc * PD;
    if (tid < 9) w3[tid] = w[c * 9 + tid];
    for (int i = tid; i < 34 * 34; i += 256) {
        int r = i / 34, cc = i % 34;
        int gy = r - 1, gx = cc - 1;
        xs[r][cc] = (gy >= 0 && gy < HD && gx >= 0 && gx < WD) ? ip[gy * WD + gx] : 0.f;
    }
    __syncthreads();
    const int tx = tid & 31, ty = tid >> 5;
    float* op = g_qkvdw + (size_t)zc * PD;
    #pragma unroll
    for (int rr = 0; rr < 4; rr++) {
        int oy = ty + rr * 8;
        float s = 0.f;
        #pragma unroll
        for (int ky = 0; ky < 3; ky++)
            #pragma unroll
            for (int kx = 0; kx < 3; kx++)
                s = fmaf(xs[oy + ky][tx + kx], w3[ky * 3 + kx], s);
        op[oy * WD + tx] = s;
    }
}

// --------------- attention Gram + softmax (coalesced, chunked) --------------
__global__ void attn_kernel2(const float* __restrict__ temp)
{
    const int bh = blockIdx.x;
    const int b = bh / HEADS, h = bh % HEADS;
    const float* q = g_qkvdw + ((size_t)b * 576 + h * CH) * PD;
    const float* kk = g_qkvdw + ((size_t)b * 576 + DIMC + h * CH) * PD;

    __shared__ float qs[CH][65], ks[CH][65];
    __shared__ float qn[CH], kn[CH], sm[CH][CH];
    const int tid = threadIdx.x;            // 576
    const int c = tid / CH, d = tid % CH;

    float acc = 0.f, accq = 0.f, acck = 0.f;
    for (int chn = 0; chn < 16; chn++) {
        #pragma unroll
        for (int i = 0; i < 3; i++) {
            int e = tid + i * 576;
            if (e < CH * 64) {
                int r = e >> 6, cc = e & 63;
                qs[r][cc] = q[(size_t)r * PD + chn * 64 + cc];
                ks[r][cc] = kk[(size_t)r * PD + chn * 64 + cc];
            }
        }
        __syncthreads();
        #pragma unroll 8
        for (int i = 0; i < 64; i++)
            acc = fmaf(qs[c][i], ks[d][i], acc);
        if (c == d) {
            #pragma unroll 8
            for (int i = 0; i < 64; i++) {
                accq = fmaf(qs[c][i], qs[c][i], accq);
                acck = fmaf(ks[c][i], ks[c][i], acck);
            }
        }
        __syncthreads();
    }
    if (c == d) {
        qn[c] = fmaxf(sqrtf(accq), 1e-12f);
        kn[c] = fmaxf(sqrtf(acck), 1e-12f);
    }
    __syncthreads();
    sm[c][d] = acc / (qn[c] * kn[d]) * temp[h];
    __syncthreads();
    if (tid < CH) {
        float m = -1e30f;
        for (int j = 0; j < CH; j++) m = fmaxf(m, sm[tid][j]);
        float e[CH]; float ssum = 0.f;
        for (int j = 0; j < CH; j++) { e[j] = expf(sm[tid][j] - m); ssum += e[j]; }
        float inv = 1.f / ssum;
        for (int j = 0; j < CH; j++)
            g_attn[((size_t)bh * CH + tid) * CH + j] = e[j] * inv;
    }
}

// ------------------------------ v gate (coalesced) ---------------------------
__global__ void vgate_kernel2(const float* __restrict__ w2, const float* __restrict__ w3)
{
    const int b = blockIdx.x;
    const float* v = g_qkvdw + ((size_t)b * 576 + 2 * DIMC) * PD;
    __shared__ float vmax[DIMC], vavg[DIMC];
    const int tid = threadIdx.x;   // 256
    const int wid = tid >> 5, lane = tid & 31;
    for (int c = wid; c < DIMC; c += 8) {
        const float* p = v + (size_t)c * PD;
        float m = -1e30f, s = 0.f;
        for (int i = lane; i < PD; i += 32) { float vv = p[i]; m = fmaxf(m, vv); s += vv; }
        #pragma unroll
        for (int off = 16; off; off >>= 1) {
            m = fmaxf(m, __shfl_xor_sync(0xFFFFFFFF, m, off));
            s += __shfl_xor_sync(0xFFFFFFFF, s, off);
        }
        if (lane == 0) { vmax[c] = m; vavg[c] = s * (1.f / (float)PD); }
    }
    __syncthreads();
    if (tid < DIMC) {
        float g = 0.f;
        for (int c = 0; c < DIMC; c++)
            g = fmaf(w2[tid * DIMC + c], vmax[c], fmaf(w3[tid * DIMC + c], vavg[c], g));
        g_gate[b * DIMC + tid] = g;
    }
}

// -------- fused dw3x3(conv4b)*gate + attention apply -> cat[192:384) ---------
__global__ __launch_bounds__(256) void dwattn2_kernel(const float* __restrict__ w4b)
{
    const int z = blockIdx.z;
    const int b = z >> 3, h = z & 7;
    const int x0 = blockIdx.x * 32, y0 = blockIdx.y * 8;
    const int tid = threadIdx.x;

    __shared__ float xs[CH][10][36];
    __shared__ float a2[CH][CH];
    __shared__ float w3s[CH][9];

    const bool interior = (blockIdx.x >= 1 && blockIdx.x <= 6 &&
                           blockIdx.y >= 1 && blockIdx.y <= 30);

    const float* tb = g_t4 + ((size_t)b * DIMC + h * CH) * HW;
    {
        int d = tid / 340, rem = tid - d * 340;
        int r = rem / 34, cx = rem - r * 34;
        if (interior) {
            for (int i = tid; i < 8160; i += 256) {
                xs[d][r][cx] = tb[(size_t)d * HW + (size_t)(y0 - 1 + r) * WW + x0 - 1 + cx];
                cx += 18; r += 7;
                if (cx >= 34) { cx -= 34; r += 1; }
                if (r >= 10) { r -= 10; d += 1; }
            }
        } else {
            for (int i = tid; i < 8160; i += 256) {
                int gy = y0 - 1 + r, gx = x0 - 1 + cx;
                float v = 0.f;
                if (gy >= 0 && gy < HH && gx >= 0 && gx < WW)
                    v = tb[(size_t)d * HW + (size_t)gy * WW + gx];
                xs[d][r][cx] = v;
                cx += 18; r += 7;
                if (cx >= 34) { cx -= 34; r += 1; }
                if (r >= 10) { r -= 10; d += 1; }
            }
        }
    }
    if (tid < CH * 9) {
        int d = tid / 9;
        w3s[d][tid % 9] = w4b[(h * CH + d) * 9 + tid % 9];
    }
    for (int i = tid; i < CH * CH; i += 256) {
        int c = i / CH, d = i % CH;
        a2[c][d] = g_attn[((size_t)(b * HEADS + h) * CH + c) * CH + d] *
                   g_gate[b * DIMC + h * CH + d];
    }
    __syncthreads();

    const int tx = tid & 31, ty = tid >> 5;
    float dw[CH];
    #pragma unroll
    for (int d = 0; d < CH; d++) {
        float s = 0.f;
        #pragma unroll
        for (int ky = 0; ky < 3; ky++)
            #pragma unroll
            for (int kx = 0; kx < 3; kx++)
                s = fmaf(xs[d][ty + ky][tx + kx], w3s[d][ky * 3 + kx], s);
        dw[d] = s;
    }
    float* ob = g_cat + ((size_t)b * 384 + DIMC + h * CH) * HW + (y0 + ty) * WW + x0 + tx;
    #pragma unroll
    for (int c = 0; c < CH; c++) {
        float s = 0.f;
        #pragma unroll
        for (int d = 0; d < CH; d++) s = fmaf(a2[c][d], dw[d], s);
        ob[(size_t)c * HW] = s;
    }
}

// ------------------------------- launch -------------------------------------
extern "C" void kernel_launch(void* const* d_in, const int* in_sizes, int n_in,
                              void* d_out, int out_size)
{
    const float* x        = (const float*)d_in[0];
    const float* w_dww    = (const float*)d_in[1];
    const float* b_dww    = (const float*)d_in[2];
    const float* w_dwh    = (const float*)d_in[3];
    const float* b_dwh    = (const float*)d_in[4];
    const float* w_dwhw   = (const float*)d_in[5];
    const float* b_dwhw   = (const float*)d_in[6];
    const float* w_conv1  = (const float*)d_in[7];
    const float* w_qkv    = (const float*)d_in[8];
    const float* w_qkvdw  = (const float*)d_in[9];
    const float* w_conv2  = (const float*)d_in[10];
    const float* w_conv3  = (const float*)d_in[11];
    const float* w_conv4a = (const float*)d_in[12];
    const float* w_conv4b = (const float*)d_in[13];
    const float* w_proj   = (const float*)d_in[14];
    const float* temp     = (const float*)d_in[15];
    float* out = (float*)d_out;

    float *p_hcatdw, *p_cat, *p_t4, *p_xdown, *p_qkv;
    __nv_bfloat16 *p_w1h, *p_w1l, *p_w4h, *p_w4l, *p_wph, *p_wpl;
    cudaGetSymbolAddress((void**)&p_hcatdw, g_hcatdw);
    cudaGetSymbolAddress((void**)&p_cat,    g_cat);
    cudaGetSymbolAddress((void**)&p_t4,     g_t4);
    cudaGetSymbolAddress((void**)&p_xdown,  g_xdown);
    cudaGetSymbolAddress((void**)&p_qkv,    g_qkv);
    cudaGetSymbolAddress((void**)&p_w1h,    g_w1h);
    cudaGetSymbolAddress((void**)&p_w1l,    g_w1l);
    cudaGetSymbolAddress((void**)&p_w4h,    g_w4h);
    cudaGetSymbolAddress((void**)&p_w4l,    g_w4l);
    cudaGetSymbolAddress((void**)&p_wph,    g_wph);
    cudaGetSymbolAddress((void**)&p_wpl,    g_wpl);

    cudaFuncSetAttribute(fgemm_kernel,
                         cudaFuncAttributeMaxDynamicSharedMemorySize, SMEMT);

    // weight splits
    convw_kernel<<<(192 * 384 + 255) / 256, 256>>>(w_conv1, p_w1h, p_w1l, 192 * 384);
    convw_kernel<<<(192 * 192 + 255) / 256, 256>>>(w_conv4a, p_w4h, p_w4l, 192 * 192);
    convw_kernel<<<(192 * 384 + 255) / 256, 256>>>(w_proj, p_wph, p_wpl, 192 * 384);

    // merged + interior-specialized high-branch depthwise stack
    highpre4_kernel<<<dim3(WW / 32, HH / 32, BATCH * DIMC), 256>>>(
        x, w_dww, b_dww, w_dwh, b_dwh, w_dwhw, b_dwhw);

    // pool
    pool_kernel<<<(BATCH * DIMC * PD + 255) / 256, 256>>>(x);

    // conv1: cat[:,0:192) = W1 @ hcatdw
    fgemm_kernel<<<dim3(HW / 128, 1, BATCH), 256, SMEMT>>>(
        p_hcatdw, 384, p_w1h, p_w1l, p_cat, 384, 0);

    // low branch
    gemm_kernel<<<dim3(PD / BN, 576 / BM, BATCH), 256>>>(
        w_qkv, p_xdown, p_qkv, DIMC, PD, (size_t)DIMC * PD, (size_t)576 * PD);
    dw3x3_small_kernel<<<BATCH * 576, 256>>>(w_qkvdw);
    attn_kernel2<<<BATCH * HEADS, 576>>>(temp);
    vgate_kernel2<<<BATCH, 256>>>(w_conv2, w_conv3);

    // conv4a: t4 = W4a @ x
    fgemm_kernel<<<dim3(HW / 128, 1, BATCH), 256, SMEMT>>>(
        x, DIMC, p_w4h, p_w4l, p_t4, DIMC, 0);

    // fused dw(conv4b)*gate + attn apply -> cat[:,192:384)
    dwattn2_kernel<<<dim3(WW / 32, HH / 8, BATCH * HEADS), 256>>>(w_conv4b);

    // proj: out = Wp @ cat
    fgemm_kernel<<<dim3(HW / 128, 1, BATCH), 256, SMEMT>>>(
        p_cat, 384, p_wph, p_wpl, out, DIMC, 0);
}

// round 16
// speedup vs baseline: 1.2081x; 1.1834x over previous
#include <cuda_runtime.h>
#include <cuda_bf16.h>
#include <cstdint>

// ---------------------------------------------------------------------------
// HybridAttention — round 15: linear-algebra compression.
//   Wf  = Wp_high @ W1           (precomputed)  -> conv1 GEMM deleted
//   W2b = Wp_low @ (attn*gate)_b (per batch)    -> attn-apply matvec deleted
//   out = Wf @ hcatdw + W2b @ dw3x3(t4)         (single dual-source GEMM)
// ---------------------------------------------------------------------------

#define DIMC   192
#define HEADS  8
#define CH     24
#define HH     256
#define WW     256
#define HW     65536
#define HD     32
#define WD     32
#define PD     1024
#define BATCH  4

// ------------------------- scratch (static device) -------------------------
__device__ float g_hcatdw[(size_t)BATCH * 384 * HW];
__device__ float g_t4    [(size_t)BATCH * DIMC * HW];
__device__ float g_t5    [(size_t)BATCH * DIMC * HW];   // dw3x3(t4)
__device__ float g_xdown [(size_t)BATCH * DIMC * PD];
__device__ float g_qkv   [(size_t)BATCH * 576 * PD];
__device__ float g_qkvdw [(size_t)BATCH * 576 * PD];
__device__ float g_attn  [(size_t)BATCH * HEADS * CH * CH];
__device__ float g_gate  [(size_t)BATCH * DIMC];
// composite + plain weights, hi/lo bf16
__device__ __nv_bfloat16 g_wfh[192 * 384], g_wfl[192 * 384];          // Wp_high@W1
__device__ __nv_bfloat16 g_w2h[BATCH * 192 * 192], g_w2l[BATCH * 192 * 192];
__device__ __nv_bfloat16 g_w4h[192 * 192], g_w4l[192 * 192];

// --------------------------- ptx helpers (sm_80 ISA) ------------------------
__device__ __forceinline__ uint32_t smem_u32(const void* p) {
    uint32_t a;
    asm("{ .reg .u64 t; cvta.to.shared.u64 t, %1; cvt.u32.u64 %0, t; }"
        : "=r"(a) : "l"(p));
    return a;
}
__device__ __forceinline__ void cpasync16(uint32_t saddr, const void* gaddr) {
    asm volatile("cp.async.cg.shared.global [%0], [%1], 16;"
                 :: "r"(saddr), "l"(gaddr));
}
__device__ __forceinline__ void cpcommit() {
    asm volatile("cp.async.commit_group;" ::: "memory");
}
template<int N> __device__ __forceinline__ void cpwait() {
    asm volatile("cp.async.wait_group %0;" :: "n"(N) : "memory");
}
__device__ __forceinline__ void ldsm4(uint32_t* r, uint32_t addr) {
    asm volatile("ldmatrix.sync.aligned.m8n8.x4.shared.b16 {%0,%1,%2,%3}, [%4];"
        : "=r"(r[0]), "=r"(r[1]), "=r"(r[2]), "=r"(r[3]) : "r"(addr));
}
__device__ __forceinline__ void ldsm4t(uint32_t* r, uint32_t addr) {
    asm volatile("ldmatrix.sync.aligned.m8n8.x4.trans.shared.b16 {%0,%1,%2,%3}, [%4];"
        : "=r"(r[0]), "=r"(r[1]), "=r"(r[2]), "=r"(r[3]) : "r"(addr));
}
__device__ __forceinline__ void mma16816(float* d, const uint32_t* a,
                                         uint32_t b0, uint32_t b1) {
    asm volatile(
        "mma.sync.aligned.m16n8k16.row.col.f32.bf16.bf16.f32 "
        "{%0,%1,%2,%3}, {%4,%5,%6,%7}, {%8,%9}, {%0,%1,%2,%3};"
        : "+f"(d[0]), "+f"(d[1]), "+f"(d[2]), "+f"(d[3])
        : "r"(a[0]), "r"(a[1]), "r"(a[2]), "r"(a[3]), "r"(b0), "r"(b1));
}
__device__ __forceinline__ uint32_t pk2(float a, float b) {
    __nv_bfloat162 t; t.x = __float2bfloat16(a); t.y = __float2bfloat16(b);
    return *reinterpret_cast<uint32_t*>(&t);
}

// ------------------------------ MMA-GEMM core -------------------------------
#define ASTR  272      // 128 px bf16 = 256B + 16 pad
#define BSTR  144      // 64 k bf16 = 128B + 16 pad
#define ATH   0
#define ATL   17408    // 64*272
#define BH    34816
#define BL    62464    // +192*144
#define SMEM1 90112
#define SMEMT (2 * SMEM1)

__device__ __forceinline__ void lda_regs(float4* r, const float* Ab, int k0, int tid) {
    #pragma unroll
    for (int i = 0; i < 8; i++) {
        int e = tid + (i << 8); int k = e >> 5, q = e & 31;
        r[i] = *reinterpret_cast<const float4*>(Ab + (size_t)(k0 + k) * HW + (q << 2));
    }
}
__device__ __forceinline__ void cvt_sts(const float4* r, char* smem, int tid) {
    #pragma unroll
    for (int i = 0; i < 8; i++) {
        int e = tid + (i << 8); int k = e >> 5, q = e & 31;
        float4 f = r[i];
        uint32_t so = (uint32_t)k * ASTR + (q << 3);
        uint2 hv, lv;
        hv.x = pk2(f.x, f.y); hv.y = pk2(f.z, f.w);
        float rx = f.x - __bfloat162float(__float2bfloat16(f.x));
        float ry = f.y - __bfloat162float(__float2bfloat16(f.y));
        float rz = f.z - __bfloat162float(__float2bfloat16(f.z));
        float rw = f.w - __bfloat162float(__float2bfloat16(f.w));
        lv.x = pk2(rx, ry); lv.y = pk2(rz, rw);
        *reinterpret_cast<uint2*>(smem + so + ATH) = hv;
        *reinterpret_cast<uint2*>(smem + so + ATL) = lv;
    }
}
__device__ __forceinline__ void ldb_async(uint32_t sbuf,
    const __nv_bfloat16* Wh, const __nv_bfloat16* Wl, int Ka, int k0, int tid) {
    #pragma unroll
    for (int i = 0; i < 6; i++) {
        int e = tid + (i << 8); int r = e >> 3, q = e & 7;
        size_t go = (size_t)r * Ka + k0 + (q << 3);
        uint32_t so = r * BSTR + (q << 4);
        cpasync16(sbuf + BH + so, Wh + go);
        cpasync16(sbuf + BL + so, Wl + go);
    }
}

// shared mainloop body (one 64-K chunk already staged in smem at `buf`)
__device__ __forceinline__ void mma_chunk(uint32_t buf, const uint32_t* aoff,
                                          uint32_t boff, float acc[2][12][4]) {
    #pragma unroll
    for (int ks = 0; ks < 4; ks++) {
        uint32_t ah[2][4], al[2][4];
        ldsm4t(ah[0], buf + ATH + aoff[0] + ks * (16 * ASTR));
        ldsm4t(ah[1], buf + ATH + aoff[1] + ks * (16 * ASTR));
        ldsm4t(al[0], buf + ATL + aoff[0] + ks * (16 * ASTR));
        ldsm4t(al[1], buf + ATL + aoff[1] + ks * (16 * ASTR));
        #pragma unroll
        for (int p = 0; p < 6; p++) {
            uint32_t bh[4], bl[4];
            uint32_t ba = buf + boff + (uint32_t)p * 16 * BSTR + ks * 32;
            ldsm4(bh, ba + BH);
            ldsm4(bl, ba + BL);
            mma16816(acc[0][2 * p],     ah[0], bh[0], bh[1]);
            mma16816(acc[1][2 * p],     ah[1], bh[0], bh[1]);
            mma16816(acc[0][2 * p + 1], ah[0], bh[2], bh[3]);
            mma16816(acc[1][2 * p + 1], ah[1], bh[2], bh[3]);
            mma16816(acc[0][2 * p],     ah[0], bl[0], bl[1]);
            mma16816(acc[1][2 * p],     ah[1], bl[0], bl[1]);
            mma16816(acc[0][2 * p + 1], ah[0], bl[2], bl[3]);
            mma16816(acc[1][2 * p + 1], ah[1], bl[2], bl[3]);
            mma16816(acc[0][2 * p],     al[0], bh[0], bh[1]);
            mma16816(acc[1][2 * p],     al[1], bh[0], bh[1]);
            mma16816(acc[0][2 * p + 1], al[0], bh[2], bh[3]);
            mma16816(acc[1][2 * p + 1], al[1], bh[2], bh[3]);
        }
    }
}
__device__ __forceinline__ void gemm_epilogue(float acc[2][12][4], float* ob,
                                              int lane, int mw, int nw) {
    const int mrow = lane >> 2;
    const int ncol = 2 * (lane & 3);
    #pragma unroll
    for (int mt = 0; mt < 2; mt++) {
        #pragma unroll
        for (int nt = 0; nt < 12; nt++) {
            int m = mw * 32 + mt * 16 + mrow;
            int n = nw * 96 + nt * 8 + ncol;
            ob[(size_t)n * HW + m]           = acc[mt][nt][0];
            ob[(size_t)(n + 1) * HW + m]     = acc[mt][nt][1];
            ob[(size_t)n * HW + m + 8]       = acc[mt][nt][2];
            ob[(size_t)(n + 1) * HW + m + 8] = acc[mt][nt][3];
        }
    }
}

// ---------------- single-source GEMM (conv4a: t4 = W4a @ x) -----------------
__global__ __launch_bounds__(256, 1) void fgemm_kernel(
    const float* __restrict__ In, int Ka,
    const __nv_bfloat16* __restrict__ Whi, const __nv_bfloat16* __restrict__ Wlo,
    float* __restrict__ Out)
{
    extern __shared__ char smem[];
    const uint32_t sb = smem_u32(smem);
    const int tid = threadIdx.x;
    const int warp = tid >> 5, lane = tid & 31;
    const int mw = warp >> 1, nw = warp & 1;
    const int b = blockIdx.z;
    const int px0 = blockIdx.x * 128;
    const int nChunks = Ka >> 6;

    const float* Ab = In + (size_t)b * Ka * HW + px0;
    float acc[2][12][4] = {};

    const int grp = lane >> 3, rr = lane & 7;
    uint32_t aoff[2];
    #pragma unroll
    for (int mt = 0; mt < 2; mt++)
        aoff[mt] = (uint32_t)((grp >> 1) * 8 + rr) * ASTR +
                   (uint32_t)(mw * 32 + mt * 16 + (grp & 1) * 8) * 2;
    const uint32_t boff = (uint32_t)(nw * 96 + rr + (grp >> 1) * 8) * BSTR +
                          (grp & 1) * 16;

    float4 ar[8];
    lda_regs(ar, Ab, 0, tid);
    ldb_async(sb, Whi, Wlo, Ka, 0, tid);
    cpcommit();

    for (int ch = 0; ch < nChunks; ch++) {
        const uint32_t bufo = (uint32_t)(ch & 1) * SMEM1;
        cvt_sts(ar, smem + bufo, tid);
        if (ch + 1 < nChunks) {
            lda_regs(ar, Ab, (ch + 1) << 6, tid);
            ldb_async(sb + ((ch + 1) & 1) * SMEM1, Whi, Wlo, Ka, (ch + 1) << 6, tid);
            cpcommit();
            cpwait<1>();
        } else {
            cpwait<0>();
        }
        __syncthreads();
        mma_chunk(sb + bufo, aoff, boff, acc);
        __syncthreads();
    }
    gemm_epilogue(acc, Out + (size_t)b * DIMC * HW + px0, lane, mw, nw);
}

// ------ dual-source GEMM: out = Wf @ hcatdw (K=384) + W2_b @ t5 (K=192) -----
__global__ __launch_bounds__(256, 1) void fgemm_dual_kernel(
    const float* __restrict__ In1,
    const __nv_bfloat16* __restrict__ Wh1, const __nv_bfloat16* __restrict__ Wl1,
    const float* __restrict__ In2,
    const __nv_bfloat16* __restrict__ Wh2, const __nv_bfloat16* __restrict__ Wl2,
    float* __restrict__ Out)
{
    extern __shared__ char smem[];
    const uint32_t sb = smem_u32(smem);
    const int tid = threadIdx.x;
    const int warp = tid >> 5, lane = tid & 31;
    const int mw = warp >> 1, nw = warp & 1;
    const int b = blockIdx.z;
    const int px0 = blockIdx.x * 128;

    const float* Ab1 = In1 + (size_t)b * 384 * HW + px0;
    const float* Ab2 = In2 + (size_t)b * 192 * HW + px0;
    const __nv_bfloat16* W2h = Wh2 + (size_t)b * 192 * 192;
    const __nv_bfloat16* W2l = Wl2 + (size_t)b * 192 * 192;

    float acc[2][12][4] = {};

    const int grp = lane >> 3, rr = lane & 7;
    uint32_t aoff[2];
    #pragma unroll
    for (int mt = 0; mt < 2; mt++)
        aoff[mt] = (uint32_t)((grp >> 1) * 8 + rr) * ASTR +
                   (uint32_t)(mw * 32 + mt * 16 + (grp & 1) * 8) * 2;
    const uint32_t boff = (uint32_t)(nw * 96 + rr + (grp >> 1) * 8) * BSTR +
                          (grp & 1) * 16;

    float4 ar[8];
    lda_regs(ar, Ab1, 0, tid);
    ldb_async(sb, Wh1, Wl1, 384, 0, tid);
    cpcommit();

    for (int ch = 0; ch < 9; ch++) {              // 6 chunks of In1 + 3 of In2
        const uint32_t bufo = (uint32_t)(ch & 1) * SMEM1;
        cvt_sts(ar, smem + bufo, tid);
        if (ch + 1 < 9) {
            int nx = ch + 1;
            if (nx < 6) {
                lda_regs(ar, Ab1, nx << 6, tid);
                ldb_async(sb + (nx & 1) * SMEM1, Wh1, Wl1, 384, nx << 6, tid);
            } else {
                lda_regs(ar, Ab2, (nx - 6) << 6, tid);
                ldb_async(sb + (nx & 1) * SMEM1, W2h, W2l, 192, (nx - 6) << 6, tid);
            }
            cpcommit();
            cpwait<1>();
        } else {
            cpwait<0>();
        }
        __syncthreads();
        mma_chunk(sb + bufo, aoff, boff, acc);
        __syncthreads();
    }
    gemm_epilogue(acc, Out + (size_t)b * DIMC * HW + px0, lane, mw, nw);
}

// ----------------------- weight convert (hi/lo) -----------------------------
__global__ void convw_kernel(const float* __restrict__ w,
                             __nv_bfloat16* __restrict__ hi,
                             __nv_bfloat16* __restrict__ lo, int n)
{
    int i = blockIdx.x * 256 + threadIdx.x;
    if (i >= n) return;
    float v = w[i];
    __nv_bfloat16 h = __float2bfloat16(v);
    hi[i] = h;
    lo[i] = __float2bfloat16(v - __bfloat162float(h));
}

// ------------------ Wf = Wp[:, :192] @ W1  (fp32, then split) ---------------
__global__ __launch_bounds__(384) void composeWf_kernel(
    const float* __restrict__ wp, const float* __restrict__ w1)
{
    const int o = blockIdx.x;          // 192
    const int k = threadIdx.x;         // 384
    __shared__ float wr[192];
    if (k < 192) wr[k] = wp[o * 384 + k];
    __syncthreads();
    float s = 0.f;
    #pragma unroll 8
    for (int c = 0; c < 192; c++)
        s = fmaf(wr[c], w1[c * 384 + k], s);
    __nv_bfloat16 h = __float2bfloat16(s);
    g_wfh[o * 384 + k] = h;
    g_wfl[o * 384 + k] = __float2bfloat16(s - __bfloat162float(h));
}

// --- W2_b[o][dg] = gate[b][dg] * sum_c Wp[o][192+h*24+c] * attn[b,h][c][d] --
__global__ __launch_bounds__(192) void composeW2_kernel(const float* __restrict__ wp)
{
    const int z = blockIdx.x;          // b*192 + o
    const int b = z / 192, o = z - b * 192;
    const int dg = threadIdx.x;        // 192
    const int h = dg / 24, d = dg - h * 24;
    const float* at = g_attn + ((size_t)(b * HEADS + h) * CH) * CH + d;  // [c][d] stride CH
    const float* wpr = wp + o * 384 + 192 + h * 24;
    float s = 0.f;
    #pragma unroll
    for (int c = 0; c < 24; c++)
        s = fmaf(wpr[c], at[c * CH], s);
    s *= g_gate[b * DIMC + dg];
    __nv_bfloat16 hh = __float2bfloat16(s);
    size_t idx = ((size_t)b * DIMC + o) * DIMC + dg;
    g_w2h[idx] = hh;
    g_w2l[idx] = __float2bfloat16(s - __bfloat162float(hh));
}

// ------------------------------ fp32 SGEMM (qkv only) ------------------------
#define BM 64
#define BN 128
#define BKK 16

__global__ __launch_bounds__(256) void gemm_kernel(
    const float* __restrict__ Wt, const float* __restrict__ In,
    float* __restrict__ Out, int K, int N, size_t inBS, size_t outBS)
{
    const int b = blockIdx.z;
    const float* Ib = In + (size_t)b * inBS;
    float* Ob = Out + (size_t)b * outBS;
    const int m0 = blockIdx.y * BM;
    const int n0 = blockIdx.x * BN;

    __shared__ float Ws[BKK][BM];
    __shared__ float Is[BKK][BN];

    const int tid = threadIdx.x;
    const int tx = tid & 15;
    const int ty = tid >> 4;

    float acc[4][8] = {};

    for (int k0 = 0; k0 < K; k0 += BKK) {
        #pragma unroll
        for (int i = 0; i < 4; i++) {
            int e = tid + i * 256;
            int m = e >> 4, k = e & 15;
            Ws[k][m] = Wt[(size_t)(m0 + m) * K + k0 + k];
        }
        #pragma unroll
        for (int i = 0; i < 2; i++) {
            int e = tid + i * 256;
            int k = e >> 5, n4 = e & 31;
            float4 v = *reinterpret_cast<const float4*>(
                &Ib[(size_t)(k0 + k) * N + n0 + n4 * 4]);
            *reinterpret_cast<float4*>(&Is[k][n4 * 4]) = v;
        }
        __syncthreads();
        #pragma unroll
        for (int k = 0; k < BKK; k++) {
            float4 av = *reinterpret_cast<const float4*>(&Ws[k][ty * 4]);
            float4 b0 = *reinterpret_cast<const float4*>(&Is[k][tx * 8]);
            float4 b1 = *reinterpret_cast<const float4*>(&Is[k][tx * 8 + 4]);
            float a[4] = {av.x, av.y, av.z, av.w};
            float bb[8] = {b0.x, b0.y, b0.z, b0.w, b1.x, b1.y, b1.z, b1.w};
            #pragma unroll
            for (int i = 0; i < 4; i++)
                #pragma unroll
                for (int j = 0; j < 8; j++)
                    acc[i][j] = fmaf(a[i], bb[j], acc[i][j]);
        }
        __syncthreads();
    }
    #pragma unroll
    for (int i = 0; i < 4; i++) {
        size_t row = (size_t)(m0 + ty * 4 + i) * N + n0 + tx * 8;
        *reinterpret_cast<float4*>(&Ob[row]) =
            make_float4(acc[i][0], acc[i][1], acc[i][2], acc[i][3]);
        *reinterpret_cast<float4*>(&Ob[row + 4]) =
            make_float4(acc[i][4], acc[i][5], acc[i][6], acc[i][7]);
    }
}

// ---- merged dual-branch strip conv + 3x3 dw, interior-specialized ----------
__global__ __launch_bounds__(256) void highpre4_kernel(
    const float* __restrict__ x,
    const float* __restrict__ w_dww, const float* __restrict__ b_dww,
    const float* __restrict__ w_dwh, const float* __restrict__ b_dwh,
    const float* __restrict__ w_dwhw, const float* __restrict__ b_dwhw)
{
    const int zc = blockIdx.z;               // b*192 + c
    const int b = zc / DIMC, c = zc % DIMC;
    const int y0 = blockIdx.y * 32, x0 = blockIdx.x * 32;
    const float* xp = x + (size_t)zc * HW;

    __shared__ float xs[44][48];
    __shared__ float sh[34][36];
    __shared__ float sv[34][36];
    __shared__ float wgt[40];

    const int tid = threadIdx.x;

    if (tid < 11)       wgt[tid] = w_dww[c * 11 + tid];
    else if (tid < 22)  wgt[tid] = w_dwh[c * 11 + tid - 11];
    else if (tid < 31)  wgt[tid] = w_dwhw[c * 9 + tid - 22];
    else if (tid < 40)  wgt[tid] = w_dwhw[(c + DIMC) * 9 + tid - 31];

    const bool interior = (blockIdx.x >= 1 && blockIdx.x <= 6 &&
                           blockIdx.y >= 1 && blockIdx.y <= 6);
    const float bhv = b_dww[c], bvv = b_dwh[c];

    if (interior) {
        for (int idx = tid; idx < 528; idx += 256) {
            int r = idx / 12, q = idx - r * 12;
            float4 v = *reinterpret_cast<const float4*>(
                xp + (size_t)(y0 - 6 + r) * WW + (x0 - 8) + (q << 2));
            *reinterpret_cast<float4*>(&xs[r][q << 2]) = v;
        }
        __syncthreads();

        for (int item = tid; item < 306; item += 256) {
            int r = item / 9, g = item - r * 9;
            int c0 = g << 2;
            float4 q0 = *reinterpret_cast<const float4*>(&xs[r + 5][c0]);
            float4 q1 = *reinterpret_cast<const float4*>(&xs[r + 5][c0 + 4]);
            float4 q2 = *reinterpret_cast<const float4*>(&xs[r + 5][c0 + 8]);
            float4 q3 = *reinterpret_cast<const float4*>(&xs[r + 5][c0 + 12]);
            float v[16] = {q0.x, q0.y, q0.z, q0.w, q1.x, q1.y, q1.z, q1.w,
                           q2.x, q2.y, q2.z, q2.w, q3.x, q3.y, q3.z, q3.w};
            #pragma unroll
            for (int jj = 0; jj < 4; jj++) {
                int cc = c0 + jj;
                if (cc < 34) {
                    float s = bhv;
                    #pragma unroll
                    for (int k = 0; k < 11; k++) s = fmaf(v[jj + 2 + k], wgt[k], s);
                    sh[r][cc] = s;
                }
            }
        }
        for (int item = tid; item < 306; item += 256) {
            int gi = item / 34, cc = item - gi * 34;
            int r0 = gi << 2;
            float v[14];
            #pragma unroll
            for (int k = 0; k < 14; k++) v[k] = xs[r0 + k][cc + 7];
            #pragma unroll
            for (int ii = 0; ii < 4; ii++) {
                int r = r0 + ii;
                if (r < 34) {
                    float s = bvv;
                    #pragma unroll
                    for (int k = 0; k < 11; k++) s = fmaf(v[ii + k], wgt[11 + k], s);
                    sv[r][cc] = s;
                }
            }
        }
    } else {
        {
            int r = tid / 44, cc = tid - r * 44;
            #pragma unroll
            for (int it = 0; it < 8; it++) {
                if (r < 44) {
                    int gy = y0 - 6 + r, gx = x0 - 6 + cc;
                    float v = 0.f;
                    if (gy >= 0 && gy < HH && gx >= 0 && gx < WW) v = xp[gy * WW + gx];
                    xs[r][cc] = v;
                }
                r += 5; cc += 36;
                if (cc >= 44) { cc -= 44; r += 1; }
            }
        }
        __syncthreads();

        for (int item = tid; item < 306; item += 256) {
            int r = item / 9, g = item - r * 9;
            int c0 = g << 2;
            float4 q0 = *reinterpret_cast<const float4*>(&xs[r + 5][c0]);
            float4 q1 = *reinterpret_cast<const float4*>(&xs[r + 5][c0 + 4]);
            float4 q2 = *reinterpret_cast<const float4*>(&xs[r + 5][c0 + 8]);
            float4 q3 = *reinterpret_cast<const float4*>(&xs[r + 5][c0 + 12]);
            float v[16] = {q0.x, q0.y, q0.z, q0.w, q1.x, q1.y, q1.z, q1.w,
                           q2.x, q2.y, q2.z, q2.w, q3.x, q3.y, q3.z, q3.w};
            int gy = y0 - 1 + r;
            bool rowok = (gy >= 0 && gy < HH);
            #pragma unroll
            for (int jj = 0; jj < 4; jj++) {
                int cc = c0 + jj;
                if (cc < 34) {
                    float s = bhv;
                    #pragma unroll
                    for (int k = 0; k < 11; k++) s = fmaf(v[jj + k], wgt[k], s);
                    int gx = x0 - 1 + cc;
                    sh[r][cc] = (rowok && gx >= 0 && gx < WW) ? s : 0.f;
                }
            }
        }
        for (int item = tid; item < 306; item += 256) {
            int gi = item / 34, cc = item - gi * 34;
            int r0 = gi << 2;
            float v[14];
            #pragma unroll
            for (int k = 0; k < 14; k++) v[k] = xs[r0 + k][cc + 5];
            int gx = x0 - 1 + cc;
            bool colok = (gx >= 0 && gx < WW);
            #pragma unroll
            for (int ii = 0; ii < 4; ii++) {
                int r = r0 + ii;
                if (r < 34) {
                    float s = bvv;
                    #pragma unroll
                    for (int k = 0; k < 11; k++) s = fmaf(v[ii + k], wgt[11 + k], s);
                    int gy = y0 - 1 + r;
                    sv[r][cc] = (colok && gy >= 0 && gy < HH) ? s : 0.f;
                }
            }
        }
    }
    __syncthreads();

    const float b3h = b_dwhw[c], b3v = b_dwhw[c + DIMC];
    float* oph = g_hcatdw + ((size_t)b * 384 + c) * HW;
    float* opv = g_hcatdw + ((size_t)b * 384 + DIMC + c) * HW;
    {
        int oy = tid >> 3, g = tid & 7;
        int c0 = g << 2;
        float hv[3][6], vv[3][6];
        #pragma unroll
        for (int ky = 0; ky < 3; ky++) {
            float4 a = *reinterpret_cast<const float4*>(&sh[oy + ky][c0]);
            float2 b2 = *reinterpret_cast<const float2*>(&sh[oy + ky][c0 + 4]);
            hv[ky][0] = a.x; hv[ky][1] = a.y; hv[ky][2] = a.z; hv[ky][3] = a.w;
            hv[ky][4] = b2.x; hv[ky][5] = b2.y;
            float4 av = *reinterpret_cast<const float4*>(&sv[oy + ky][c0]);
            float2 bv2 = *reinterpret_cast<const float2*>(&sv[oy + ky][c0 + 4]);
            vv[ky][0] = av.x; vv[ky][1] = av.y; vv[ky][2] = av.z; vv[ky][3] = av.w;
            vv[ky][4] = bv2.x; vv[ky][5] = bv2.y;
        }
        float r1[4], r2[4];
        #pragma unroll
        for (int jj = 0; jj < 4; jj++) {
            float s1 = b3h, s2 = b3v;
            #pragma unroll
            for (int ky = 0; ky < 3; ky++)
                #pragma unroll
                for (int kx = 0; kx < 3; kx++) {
                    s1 = fmaf(hv[ky][jj + kx], wgt[22 + ky * 3 + kx], s1);
                    s2 = fmaf(vv[ky][jj + kx], wgt[31 + ky * 3 + kx], s2);
                }
            r1[jj] = s1; r2[jj] = s2;
        }
        size_t o = (size_t)(y0 + oy) * WW + x0 + c0;
        *reinterpret_cast<float4*>(oph + o) = make_float4(r1[0], r1[1], r1[2], r1[3]);
        *reinterpret_cast<float4*>(opv + o) = make_float4(r2[0], r2[1], r2[2], r2[3]);
    }
}

// ----------------------------- avg pool 8x8 (float4) -------------------------
__global__ void pool_kernel(const float* __restrict__ x)
{
    int idx = blockIdx.x * 256 + threadIdx.x;
    if (idx >= BATCH * DIMC * PD) return;
    int p = idx % PD; int bc = idx / PD;
    int yd = p / WD, xd = p % WD;
    const float* xp = x + (size_t)bc * HW + (yd * 8) * WW + xd * 8;
    float s = 0.f;
    #pragma unroll
    for (int i = 0; i < 8; i++) {
        float4 a = *reinterpret_cast<const float4*>(xp + i * WW);
        float4 bq = *reinterpret_cast<const float4*>(xp + i * WW + 4);
        s += (a.x + a.y + a.z + a.w) + (bq.x + bq.y + bq.z + bq.w);
    }
    g_xdown[idx] = s * (1.f / 64.f);
}

// ------------------------- 3x3 depthwise (32x32) ----------------------------
__global__ __launch_bounds__(256) void dw3x3_small_kernel(const float* __restrict__ w)
{
    const int zc = blockIdx.x;
    const int c = zc % 576;
    __shared__ float xs[34][34];
    __shared__ float w3[9];
    const int tid = threadIdx.x;
    const float* ip = g_qkv + (size_t)zc * PD;
    if (tid < 9) w3[tid] = w[c * 9 + tid];
    for (int i = tid; i < 34 * 34; i += 256) {
        int r = i / 34, cc = i % 34;
        int gy = r - 1, gx = cc - 1;
        xs[r][cc] = (gy >= 0 && gy < HD && gx >= 0 && gx < WD) ? ip[gy * WD + gx] : 0.f;
    }
    __syncthreads();
    const int tx = tid & 31, ty = tid >> 5;
    float* op = g_qkvdw + (size_t)zc * PD;
    #pragma unroll
    for (int rr = 0; rr < 4; rr++) {
        int oy = ty + rr * 8;
        float s = 0.f;
        #pragma unroll
        for (int ky = 0; ky < 3; ky++)
            #pragma unroll
            for (int kx = 0; kx < 3; kx++)
                s = fmaf(xs[oy + ky][tx + kx], w3[ky * 3 + kx], s);
        op[oy * WD + tx] = s;
    }
}

// ------------------- plain 3x3 depthwise on t4 -> t5 (256x256) --------------
__global__ __launch_bounds__(256) void dw3x3_t4_kernel(const float* __restrict__ w)
{
    const int zc = blockIdx.z;                 // b*192 + c
    const int c = zc % DIMC;
    const int y0 = blockIdx.y * 32, x0 = blockIdx.x * 32;
    const float* ip = g_t4 + (size_t)zc * HW;
    __shared__ float xs[34][36];
    __shared__ float w3[9];
    const int tid = threadIdx.x;
    if (tid < 9) w3[tid] = w[c * 9 + tid];
    for (int i = tid; i < 34 * 34; i += 256) {
        int r = i / 34, cc = i - (i / 34) * 34;
        int gy = y0 - 1 + r, gx = x0 - 1 + cc;
        xs[r][cc] = (gy >= 0 && gy < HH && gx >= 0 && gx < WW) ? ip[gy * WW + gx] : 0.f;
    }
    __syncthreads();
    const int tx = tid & 31, ty = tid >> 5;
    float* op = g_t5 + (size_t)zc * HW;
    #pragma unroll
    for (int rr = 0; rr < 4; rr++) {
        int oy = ty + rr * 8;
        float s = 0.f;
        #pragma unroll
        for (int ky = 0; ky < 3; ky++)
            #pragma unroll
            for (int kx = 0; kx < 3; kx++)
                s = fmaf(xs[oy + ky][tx + kx], w3[ky * 3 + kx], s);
        op[(y0 + oy) * WW + x0 + tx] = s;
    }
}

// --------------- attention Gram + softmax (coalesced, chunked) --------------
__global__ void attn_kernel2(const float* __restrict__ temp)
{
    const int bh = blockIdx.x;
    const int b = bh / HEADS, h = bh % HEADS;
    const float* q = g_qkvdw + ((size_t)b * 576 + h * CH) * PD;
    const float* kk = g_qkvdw + ((size_t)b * 576 + DIMC + h * CH) * PD;

    __shared__ float qs[CH][65], ks[CH][65];
    __shared__ float qn[CH], kn[CH], sm[CH][CH];
    const int tid = threadIdx.x;            // 576
    const int c = tid / CH, d = tid % CH;

    float acc = 0.f, accq = 0.f, acck = 0.f;
    for (int chn = 0; chn < 16; chn++) {
        #pragma unroll
        for (int i = 0; i < 3; i++) {
            int e = tid + i * 576;
            if (e < CH * 64) {
                int r = e >> 6, cc = e & 63;
                qs[r][cc] = q[(size_t)r * PD + chn * 64 + cc];
                ks[r][cc] = kk[(size_t)r * PD + chn * 64 + cc];
            }
        }
        __syncthreads();
        #pragma unroll 8
        for (int i = 0; i < 64; i++)
            acc = fmaf(qs[c][i], ks[d][i], acc);
        if (c == d) {
            #pragma unroll 8
            for (int i = 0; i < 64; i++) {
                accq = fmaf(qs[c][i], qs[c][i], accq);
                acck = fmaf(ks[c][i], ks[c][i], acck);
            }
        }
        __syncthreads();
    }
    if (c == d) {
        qn[c] = fmaxf(sqrtf(accq), 1e-12f);
        kn[c] = fmaxf(sqrtf(acck), 1e-12f);
    }
    __syncthreads();
    sm[c][d] = acc / (qn[c] * kn[d]) * temp[h];
    __syncthreads();
    if (tid < CH) {
        float m = -1e30f;
        for (int j = 0; j < CH; j++) m = fmaxf(m, sm[tid][j]);
        float e[CH]; float ssum = 0.f;
        for (int j = 0; j < CH; j++) { e[j] = expf(sm[tid][j] - m); ssum += e[j]; }
        float inv = 1.f / ssum;
        for (int j = 0; j < CH; j++)
            g_attn[((size_t)bh * CH + tid) * CH + j] = e[j] * inv;
    }
}

// ------------------------------ v gate (coalesced) ---------------------------
__global__ void vgate_kernel2(const float* __restrict__ w2, const float* __restrict__ w3)
{
    const int b = blockIdx.x;
    const float* v = g_qkvdw + ((size_t)b * 576 + 2 * DIMC) * PD;
    __shared__ float vmax[DIMC], vavg[DIMC];
    const int tid = threadIdx.x;   // 256
    const int wid = tid >> 5, lane = tid & 31;
    for (int c = wid; c < DIMC; c += 8) {
        const float* p = v + (size_t)c * PD;
        float m = -1e30f, s = 0.f;
        for (int i = lane; i < PD; i += 32) { float vv = p[i]; m = fmaxf(m, vv); s += vv; }
        #pragma unroll
        for (int off = 16; off; off >>= 1) {
            m = fmaxf(m, __shfl_xor_sync(0xFFFFFFFF, m, off));
            s += __shfl_xor_sync(0xFFFFFFFF, s, off);
        }
        if (lane == 0) { vmax[c] = m; vavg[c] = s * (1.f / (float)PD); }
    }
    __syncthreads();
    if (tid < DIMC) {
        float g = 0.f;
        for (int c = 0; c < DIMC; c++)
            g = fmaf(w2[tid * DIMC + c], vmax[c], fmaf(w3[tid * DIMC + c], vavg[c], g));
        g_gate[b * DIMC + tid] = g;
    }
}

// ------------------------------- launch -------------------------------------
extern "C" void kernel_launch(void* const* d_in, const int* in_sizes, int n_in,
                              void* d_out, int out_size)
{
    const float* x        = (const float*)d_in[0];
    const float* w_dww    = (const float*)d_in[1];
    const float* b_dww    = (const float*)d_in[2];
    const float* w_dwh    = (const float*)d_in[3];
    const float* b_dwh    = (const float*)d_in[4];
    const float* w_dwhw   = (const float*)d_in[5];
    const float* b_dwhw   = (const float*)d_in[6];
    const float* w_conv1  = (const float*)d_in[7];
    const float* w_qkv    = (const float*)d_in[8];
    const float* w_qkvdw  = (const float*)d_in[9];
    const float* w_conv2  = (const float*)d_in[10];
    const float* w_conv3  = (const float*)d_in[11];
    const float* w_conv4a = (const float*)d_in[12];
    const float* w_conv4b = (const float*)d_in[13];
    const float* w_proj   = (const float*)d_in[14];
    const float* temp     = (const float*)d_in[15];
    float* out = (float*)d_out;

    float *p_hcatdw, *p_t4, *p_t5, *p_xdown, *p_qkv;
    __nv_bfloat16 *p_wfh, *p_wfl, *p_w2h, *p_w2l, *p_w4h, *p_w4l;
    cudaGetSymbolAddress((void**)&p_hcatdw, g_hcatdw);
    cudaGetSymbolAddress((void**)&p_t4,     g_t4);
    cudaGetSymbolAddress((void**)&p_t5,     g_t5);
    cudaGetSymbolAddress((void**)&p_xdown,  g_xdown);
    cudaGetSymbolAddress((void**)&p_qkv,    g_qkv);
    cudaGetSymbolAddress((void**)&p_wfh,    g_wfh);
    cudaGetSymbolAddress((void**)&p_wfl,    g_wfl);
    cudaGetSymbolAddress((void**)&p_w2h,    g_w2h);
    cudaGetSymbolAddress((void**)&p_w2l,    g_w2l);
    cudaGetSymbolAddress((void**)&p_w4h,    g_w4h);
    cudaGetSymbolAddress((void**)&p_w4l,    g_w4l);

    cudaFuncSetAttribute(fgemm_kernel,
                         cudaFuncAttributeMaxDynamicSharedMemorySize, SMEMT);
    cudaFuncSetAttribute(fgemm_dual_kernel,
                         cudaFuncAttributeMaxDynamicSharedMemorySize, SMEMT);

    // #1 w4 split, #2 composite Wf
    convw_kernel<<<(192 * 192 + 255) / 256, 256>>>(w_conv4a, p_w4h, p_w4l, 192 * 192);
    composeWf_kernel<<<192, 384>>>(w_proj, w_conv1);

    // #3 high-branch depthwise stack, #4 pool, #5 qkv gemm
    highpre4_kernel<<<dim3(WW / 32, HH / 32, BATCH * DIMC), 256>>>(
        x, w_dww, b_dww, w_dwh, b_dwh, w_dwhw, b_dwhw);
    pool_kernel<<<(BATCH * DIMC * PD + 255) / 256, 256>>>(x);
    gemm_kernel<<<dim3(PD / BN, 576 / BM, BATCH), 256>>>(
        w_qkv, p_xdown, p_qkv, DIMC, PD, (size_t)DIMC * PD, (size_t)576 * PD);

    // #6 conv4a: t4 = W4a @ x   (profiled launch)
    fgemm_kernel<<<dim3(HW / 128, 1, BATCH), 256, SMEMT>>>(
        x, DIMC, p_w4h, p_w4l, p_t4);

    // low branch small kernels
    dw3x3_small_kernel<<<BATCH * 576, 256>>>(w_qkvdw);
    attn_kernel2<<<BATCH * HEADS, 576>>>(temp);
    vgate_kernel2<<<BATCH, 256>>>(w_conv2, w_conv3);
    composeW2_kernel<<<BATCH * 192, 192>>>(w_proj);

    // t5 = dw3x3(t4)
    dw3x3_t4_kernel<<<dim3(WW / 32, HH / 32, BATCH * DIMC), 256>>>(w_conv4b);

    // out = Wf @ hcatdw + W2_b @ t5
    fgemm_dual_kernel<<<dim3(HW / 128, 1, BATCH), 256, SMEMT>>>(
        p_hcatdw, p_wfh, p_wfl, p_t5, p_w2h, p_w2l, out);
}